// round 14
// baseline (speedup 1.0000x reference)
#include <cuda_runtime.h>
#include <cuda_bf16.h>
#include <math.h>
#include <stdint.h>

#define B_ 32
#define T_ 64
#define S_ 64
#define V_ 32000
#define E_ 512
#define U_ 1024
#define NBLK 148

// ---------------- scratch (static device globals; no allocs) ----------------
__device__ float g_emb  [B_*T_*E_];
__device__ float g_keys [B_*S_*U_];
__device__ float g_zpart[40*B_*4*U_];     // z split-k partials (40 x 64k chunks)
__device__ float g_qpart[16*B_*U_];       // q partials (16 chunks)
__device__ float g_apart[32*B_*U_];       // attnout partials (32 chunks)
__device__ float g_aprev[B_*U_];
__device__ float g_h    [B_*U_];
__device__ float g_c    [B_*U_];
__device__ float g_ctx  [B_*U_];
__device__ unsigned int g_sync_ctr;
// bf16-split operands for tensor-core output GEMM
__device__ __nv_bfloat16 g_Ah[B_*T_*U_];
__device__ __nv_bfloat16 g_Al[B_*T_*U_];
__device__ __nv_bfloat16 g_Bh[V_*U_];
__device__ __nv_bfloat16 g_Bl[V_*U_];

__device__ __forceinline__ float tanh_fast(float x){
    float r; asm("tanh.approx.f32 %0, %1;" : "=f"(r) : "f"(x)); return r;
}
__device__ __forceinline__ float sigmoid_acc(float x){
    return 1.0f / (1.0f + expf(-x));
}

// ---- packed f32x2 helpers ----
__device__ __forceinline__ unsigned long long pack2(float a, float b){
    unsigned long long r;
    asm("mov.b64 %0, {%1, %2};" : "=l"(r) : "f"(a), "f"(b));
    return r;
}
__device__ __forceinline__ void unpack2(unsigned long long v, float& a, float& b){
    asm("mov.b64 {%0, %1}, %2;" : "=f"(a), "=f"(b) : "l"(v));
}
#define FMA2(acc, x, w) \
    asm("fma.rn.f32x2 %0, %1, %2, %0;" : "+l"(acc) : "l"(x), "l"(w))

// ---- sub-block (128-thread) named barrier ----
__device__ __forceinline__ void subbar(int sub){
    asm volatile("bar.sync %0, 128;" :: "r"(sub + 1) : "memory");
}

// ---- grid-wide barrier (monotonic counter; reset each launch) ----
__global__ void reset_sync(){ g_sync_ctr = 0u; }

__device__ __forceinline__ void gsync(unsigned int& expect){
    __syncthreads();
    if (threadIdx.x == 0){
        expect += NBLK;
        __threadfence();
        atomicAdd(&g_sync_ctr, 1u);
        unsigned int v;
        while (true){
            asm volatile("ld.acquire.gpu.u32 %0, [%1];" : "=r"(v) : "l"(&g_sync_ctr));
            if (v >= expect) break;
            __nanosleep(64);
        }
    }
    __syncthreads();
}

// ---------------- init h/c ----------------
__global__ void init_hc(const float* __restrict__ h0, const float* __restrict__ c0){
    int i = blockIdx.x * blockDim.x + threadIdx.x;
    if (i < B_*U_){ g_h[i] = h0[i]; g_c[i] = c0[i]; }
}

// ---------------- embedding gather ----------------
__global__ void embed_gather(const int* __restrict__ y, const float* __restrict__ emb){
    int bt = blockIdx.x;
    int b = bt / T_, t = bt % T_;
    int tok = (t == 0) ? 1 : y[b*T_ + t - 1];
    const float4* src = (const float4*)(emb + (long long)tok * E_);
    float4* dst = (float4*)(g_emb + (long long)bt * E_);
    int i = threadIdx.x;
    if (i < E_/4) dst[i] = src[i];
}

// ================= persistent recurrence kernel ============================
// Generic 64k x 128j x 32b split-k GEMM tile. N = output row stride (4096/1024).
template<int N>
__device__ __forceinline__ void tile64(float* xs, int stid, int sub,
        const float* __restrict__ xp, long long xst,
        const float* __restrict__ w,      // weight base + row0*N + j
        float* __restrict__ outp){        // partial base + kb*B*N + j
    subbar(sub);
    int b = stid >> 2, kq = stid & 3;
    #pragma unroll
    for (int i = 0; i < 4; i++){
        int k = kq*16 + i*4;
        float4 v = *(const float4*)(xp + b*xst + k);
        xs[(k+0)*36+b] = v.x; xs[(k+1)*36+b] = v.y;
        xs[(k+2)*36+b] = v.z; xs[(k+3)*36+b] = v.w;
    }
    subbar(sub);

    unsigned long long acc2[16];
    #pragma unroll
    for (int i = 0; i < 16; i++) acc2[i] = 0ull;

    #pragma unroll 4
    for (int k = 0; k < 64; k += 4){
        float w0 = w[(k+0)*N];
        float w1 = w[(k+1)*N];
        float w2 = w[(k+2)*N];
        float w3 = w[(k+3)*N];
        #pragma unroll
        for (int kk = 0; kk < 4; kk++){
            float wk = (kk==0)?w0:(kk==1)?w1:(kk==2)?w2:w3;
            unsigned long long wk2 = pack2(wk, wk);
            #pragma unroll
            for (int b4 = 0; b4 < 8; b4++){
                const float4 xv = *(const float4*)&xs[(k+kk)*36 + b4*4];
                unsigned long long x01 = pack2(xv.x, xv.y);
                unsigned long long x23 = pack2(xv.z, xv.w);
                FMA2(acc2[b4*2+0], x01, wk2);
                FMA2(acc2[b4*2+1], x23, wk2);
            }
        }
    }
    #pragma unroll
    for (int p = 0; p < 16; p++){
        float v0, v1; unpack2(acc2[p], v0, v1);
        outp[(long long)(2*p+0)*N] = v0;
        outp[(long long)(2*p+1)*N] = v1;
    }
}

__device__ __forceinline__ void lstm_elem(int idx, const float* __restrict__ bias){
    int b = idx >> 10, u = idx & 1023;
    float zi = bias[u], zj = bias[U_+u], zf = bias[2*U_+u], zo = bias[3*U_+u];
    #pragma unroll 8
    for (int p = 0; p < 40; p++){
        const float* zp = g_zpart + ((long long)p*B_ + b)*4096;
        zi += zp[u]; zj += zp[U_+u]; zf += zp[2*U_+u]; zo += zp[3*U_+u];
    }
    float c  = g_c[idx];
    float cn = sigmoid_acc(zf + 1.0f) * c + sigmoid_acc(zi) * tanhf(zj);
    g_c[idx] = cn;
    g_h[idx] = sigmoid_acc(zo) * tanhf(cn);
}

__device__ __forceinline__ void attn_block(float* psm, int tid, int b,
        const float* __restrict__ enc, const float* __restrict__ v){
    float* q_s  = psm;          // 1024
    float* sc_s = psm + 1024;   // 64
    float* al_s = psm + 1088;   // 64

    for (int u = tid; u < U_; u += 512){
        float s = 0.0f;
        #pragma unroll
        for (int p = 0; p < 16; p++)
            s += g_qpart[((long long)p*B_ + b)*U_ + u];
        q_s[u] = s;
    }
    __syncthreads();

    int warp = tid >> 5, lane = tid & 31;
    #pragma unroll
    for (int si = 0; si < 4; si++){
        int s = warp*4 + si;
        const float* kp = g_keys + (long long)(b*S_ + s)*U_;
        float p = 0.f;
        for (int u = lane; u < U_; u += 32)
            p = fmaf(tanh_fast(kp[u] + q_s[u]), v[u], p);
        #pragma unroll
        for (int off = 16; off; off >>= 1)
            p += __shfl_xor_sync(0xffffffffu, p, off);
        if (lane == 0) sc_s[s] = p;
    }
    __syncthreads();

    if (warp == 0){
        float s0 = sc_s[lane], s1 = sc_s[lane+32];
        float m = fmaxf(s0, s1);
        #pragma unroll
        for (int off = 16; off; off >>= 1)
            m = fmaxf(m, __shfl_xor_sync(0xffffffffu, m, off));
        float e0 = expf(s0 - m), e1 = expf(s1 - m);
        float sum = e0 + e1;
        #pragma unroll
        for (int off = 16; off; off >>= 1)
            sum += __shfl_xor_sync(0xffffffffu, sum, off);
        float inv = 1.0f / sum;
        al_s[lane]    = e0 * inv;
        al_s[lane+32] = e1 * inv;
    }
    __syncthreads();

    for (int e = tid; e < U_; e += 512){
        const float* ep = enc + (long long)b*S_*U_ + e;
        float a = 0.f;
        #pragma unroll 16
        for (int s = 0; s < S_; s++)
            a = fmaf(al_s[s], ep[(long long)s*U_], a);
        g_ctx[(long long)b*U_ + e] = a;
    }
}

// reduce attnout partials of step t-1 into aprev + bf16 split of a(t-1)
__device__ __forceinline__ void p_phase(int tid, int b, int t, bool write_aprev){
    for (int u = tid; u < U_; u += 512){
        if (t == 0){
            g_aprev[b*U_ + u] = 0.0f;
        } else {
            float s = 0.0f;
            #pragma unroll
            for (int p = 0; p < 32; p++)
                s += g_apart[((long long)p*B_ + b)*U_ + u];
            if (write_aprev) g_aprev[b*U_ + u] = s;
            __nv_bfloat16 h = __float2bfloat16(s);
            long long o = ((long long)b*T_ + (t-1))*U_ + u;
            g_Ah[o] = h;
            g_Al[o] = __float2bfloat16(s - __bfloat162float(h));
        }
    }
}

#define PS_SMEM (4*64*36*4)   // 36864 bytes: 4 sub-blocks x xs[64][36]

__global__ __launch_bounds__(512, 1)
void step_persist(const float* __restrict__ Wx, const float* __restrict__ Wh,
                  const float* __restrict__ bias, const float* __restrict__ Wq,
                  const float* __restrict__ enc, const float* __restrict__ v_att,
                  const float* __restrict__ Wa){
    extern __shared__ float psm[];
    const int tid  = threadIdx.x;
    const int blk  = blockIdx.x;
    const int sub  = tid >> 7;
    const int stid = tid & 127;
    float* xs = psm + sub * (64*36);
    unsigned int expect = 0;

    for (int t = 0; t < T_; t++){
        // ---- P: reduce a(t-1) partials -> aprev + Ah/Al[t-1] ----
        if (blk < 32) p_phase(tid, blk, t, true);
        gsync(expect);
        // ---- Z: 1280 tiles (40 kb x 32 jb), 64k each ----
        for (int tile = blk*4 + sub; tile < 1280; tile += 4*NBLK){
            int jb = tile & 31, kb = tile >> 5;
            int j  = jb*128 + stid;
            const float* xp; long long xst; const float* w;
            if (kb < 8){
                xp = g_emb + (long long)t*E_ + kb*64; xst = (long long)T_*E_;
                w  = Wx + (long long)(kb*64)*4096 + j;
            } else if (kb < 24){
                xp = g_aprev + (kb-8)*64; xst = U_;
                w  = Wx + (long long)(512 + (kb-8)*64)*4096 + j;
            } else {
                xp = g_h + (kb-24)*64; xst = U_;
                w  = Wh + (long long)((kb-24)*64)*4096 + j;
            }
            tile64<4096>(xs, stid, sub, xp, xst, w,
                         g_zpart + (long long)kb*B_*4096 + j);
        }
        gsync(expect);
        // ---- L: lstm pointwise (40-partial reduce) ----
        {
            int idx = blk*512 + tid;
            if (idx < B_*U_) lstm_elem(idx, bias);
        }
        gsync(expect);
        // ---- Q: 128 tiles (16 kb x 8 jb) ----
        {
            int tile = blk*4 + sub;
            if (tile < 128){
                int jb = tile & 7, kb = tile >> 3;
                int j  = jb*128 + stid;
                tile64<1024>(xs, stid, sub, g_h + kb*64, U_,
                             Wq + (long long)(kb*64)*U_ + j,
                             g_qpart + (long long)kb*B_*U_ + j);
            }
        }
        gsync(expect);
        // ---- A: softmax attention, 32 blocks ----
        if (blk < 32) attn_block(psm, tid, blk, enc, v_att);
        gsync(expect);
        // ---- O: 256 tiles (32 kb x 8 jb) ----
        {
            int tile = blk*4 + sub;
            if (tile < 256){
                int jb = tile & 7, kb = tile >> 3;
                int j  = jb*128 + stid;
                const float* xp = (kb < 16) ? (g_h + kb*64) : (g_ctx + (kb-16)*64);
                tile64<1024>(xs, stid, sub, xp, U_,
                             Wa + (long long)(kb*64)*U_ + j,
                             g_apart + (long long)kb*B_*U_ + j);
            }
        }
        gsync(expect);
    }
    // final: Ah/Al for t = 63
    if (blk < 32) p_phase(tid, blk, T_, false);
}

// ---------------- fp32 SGEMM (keys only, f32x2) ----------------
__global__ __launch_bounds__(256)
void sgemm128(const float* __restrict__ A, const float* __restrict__ Bm,
              const float* __restrict__ bias, float* __restrict__ C,
              int M, int N, int K){
    __shared__ float As[16][132];
    __shared__ float Bs[16][132];
    int tid = threadIdx.x;
    int tx = tid & 15, ty = tid >> 4;
    int row0 = blockIdx.x * 128, col0 = blockIdx.y * 128;

    int m0 = tid >> 2, kq = tid & 3;
    int kr = tid >> 5, n4 = tid & 31;

    unsigned long long acc2[8][4];
    #pragma unroll
    for (int i = 0; i < 8; i++)
        #pragma unroll
        for (int j = 0; j < 4; j++) acc2[i][j] = 0ull;

    const float* Ap  = A  + (long long)(row0 + m0)*K + kq*4;
    const float* Ap2 = Ap + (long long)64*K;
    const float* Bp  = Bm + (long long)kr*N + col0 + n4*4;
    const float* Bp2 = Bp + (long long)8*N;

    float4 pa0 = *(const float4*)Ap;
    float4 pa1 = *(const float4*)Ap2;
    float4 pb0 = *(const float4*)Bp;
    float4 pb1 = *(const float4*)Bp2;

    int nk = K >> 4;
    for (int kt = 0; kt < nk; kt++){
        As[kq*4+0][m0]    = pa0.x; As[kq*4+1][m0]    = pa0.y;
        As[kq*4+2][m0]    = pa0.z; As[kq*4+3][m0]    = pa0.w;
        As[kq*4+0][m0+64] = pa1.x; As[kq*4+1][m0+64] = pa1.y;
        As[kq*4+2][m0+64] = pa1.z; As[kq*4+3][m0+64] = pa1.w;
        *(float4*)&Bs[kr][n4*4]   = pb0;
        *(float4*)&Bs[kr+8][n4*4] = pb1;
        __syncthreads();

        if (kt + 1 < nk){
            pa0 = *(const float4*)(Ap  + (kt+1)*16);
            pa1 = *(const float4*)(Ap2 + (kt+1)*16);
            pb0 = *(const float4*)(Bp  + (long long)(kt+1)*16*N);
            pb1 = *(const float4*)(Bp2 + (long long)(kt+1)*16*N);
        }

        #pragma unroll
        for (int k = 0; k < 16; k++){
            float a[8];
            *(float4*)&a[0]  = *(const float4*)&As[k][ty*8];
            *(float4*)&a[4]  = *(const float4*)&As[k][ty*8+4];
            float4 b0 = *(const float4*)&Bs[k][tx*8];
            float4 b1 = *(const float4*)&Bs[k][tx*8+4];
            unsigned long long bb2[4];
            bb2[0] = pack2(b0.x, b0.y); bb2[1] = pack2(b0.z, b0.w);
            bb2[2] = pack2(b1.x, b1.y); bb2[3] = pack2(b1.z, b1.w);
            #pragma unroll
            for (int i = 0; i < 8; i++){
                unsigned long long ai = pack2(a[i], a[i]);
                #pragma unroll
                for (int j = 0; j < 4; j++)
                    FMA2(acc2[i][j], bb2[j], ai);
            }
        }
        __syncthreads();
    }

    float bv[8];
    #pragma unroll
    for (int j = 0; j < 8; j++) bv[j] = bias ? bias[col0 + tx*8 + j] : 0.0f;

    #pragma unroll
    for (int i = 0; i < 8; i++){
        float* cp = C + (long long)(row0 + ty*8 + i)*N + col0 + tx*8;
        float o[8];
        #pragma unroll
        for (int j = 0; j < 4; j++) unpack2(acc2[i][j], o[2*j], o[2*j+1]);
        float4 o0, o1;
        o0.x = o[0]+bv[0]; o0.y = o[1]+bv[1]; o0.z = o[2]+bv[2]; o0.w = o[3]+bv[3];
        o1.x = o[4]+bv[4]; o1.y = o[5]+bv[5]; o1.z = o[6]+bv[6]; o1.w = o[7]+bv[7];
        *(float4*)cp       = o0;
        *(float4*)(cp + 4) = o1;
    }
}

// ---------------- bf16 split + transpose: Wout[K,V] -> Bh/Bl [V,K] ---------
__global__ __launch_bounds__(256)
void split_wout(const float* __restrict__ W){
    __shared__ float s[32][33];
    int n0 = blockIdx.x * 32, k0 = blockIdx.y * 32;
    int tx = threadIdx.x & 31, ty = threadIdx.x >> 5;   // 32 x 8
    #pragma unroll
    for (int i = 0; i < 32; i += 8)
        s[ty+i][tx] = W[(long long)(k0+ty+i)*V_ + n0 + tx];   // s[k][n]
    __syncthreads();
    #pragma unroll
    for (int i = 0; i < 32; i += 8){
        int n = ty + i;
        float a = s[tx][n];                         // k = tx
        __nv_bfloat16 h = __float2bfloat16(a);
        long long o = (long long)(n0+n)*U_ + k0 + tx;
        g_Bh[o] = h;
        g_Bl[o] = __float2bfloat16(a - __bfloat162float(h));
    }
}

// ================= tensor-core output GEMM via mma.sync + ldmatrix =========
#define LDT     40
#define TEN     (128*LDT)
#define TEN_B   (TEN*2)
#define STAGE   (4*TEN)
#define STAGE_B (STAGE*2)
#define GM_SMEM (2*STAGE_B)

#define MMA16816(c, a, b) \
    asm volatile("mma.sync.aligned.m16n8k16.row.col.f32.bf16.bf16.f32 " \
        "{%0,%1,%2,%3}, {%4,%5,%6,%7}, {%8,%9}, {%0,%1,%2,%3};" \
        : "+f"((c)[0]), "+f"((c)[1]), "+f"((c)[2]), "+f"((c)[3]) \
        : "r"((a)[0]), "r"((a)[1]), "r"((a)[2]), "r"((a)[3]), \
          "r"((b)[0]), "r"((b)[1]))

#define LDSM4(R0, R1, R2, R3, ADDR) \
    asm volatile("ldmatrix.sync.aligned.m8n8.x4.shared.b16 {%0,%1,%2,%3}, [%4];" \
        : "=r"(R0), "=r"(R1), "=r"(R2), "=r"(R3) : "r"(ADDR))

__global__ __launch_bounds__(256)
void gemm_mma(const float* __restrict__ bias, float* __restrict__ C){
    extern __shared__ __nv_bfloat16 sm[];
    const int tid  = threadIdx.x;
    const int lane = tid & 31, wid = tid >> 5;
    const int wm   = wid >> 2, wn = wid & 3;
    const int g    = lane >> 2, c2 = (lane & 3) * 2;
    const long long row0 = (long long)blockIdx.x * 128;
    const long long col0 = (long long)blockIdx.y * 128;

    const uint32_t smb = (uint32_t)__cvta_generic_to_shared(sm);

    const uint32_t a_elem = (uint32_t)(wm*64 + ((lane>>3)&1)*8 + (lane&7)) * LDT
                          + (uint32_t)((lane>>4)*8);
    uint32_t b_elem[2];
    #pragma unroll
    for (int p = 0; p < 2; p++)
        b_elem[p] = (uint32_t)(wn*32 + p*16 + (lane>>4)*8 + (lane&7)) * LDT
                  + (uint32_t)(((lane>>3)&1)*8);

    const int lr = tid >> 1;
    const int lc = (tid & 1) * 16;
    const __nv_bfloat16* srcs[4] = {
        g_Ah + (row0 + lr)*U_, g_Al + (row0 + lr)*U_,
        g_Bh + (col0 + lr)*U_, g_Bl + (col0 + lr)*U_ };

    float acc[4][4][4];
    #pragma unroll
    for (int mi = 0; mi < 4; mi++)
        #pragma unroll
        for (int ni = 0; ni < 4; ni++)
            #pragma unroll
            for (int q = 0; q < 4; q++) acc[mi][ni][q] = 0.0f;

    auto issue = [&](int kt, int buf){
        __nv_bfloat16* st = sm + buf*STAGE;
        #pragma unroll
        for (int tn = 0; tn < 4; tn++){
            uint32_t d = (uint32_t)__cvta_generic_to_shared(st + tn*TEN + lr*LDT + lc);
            const __nv_bfloat16* s = srcs[tn] + kt*32 + lc;
            asm volatile(
                "cp.async.cg.shared.global [%0], [%1], 16;\n\t"
                "cp.async.cg.shared.global [%2], [%3], 16;"
                :: "r"(d), "l"(s), "r"(d + 16), "l"(s + 8) : "memory");
        }
        asm volatile("cp.async.commit_group;" ::: "memory");
    };

    issue(0, 0);
    for (int kt = 0; kt < 32; kt++){
        int buf = kt & 1;
        if (kt + 1 < 32){
            issue(kt + 1, buf ^ 1);
            asm volatile("cp.async.wait_group 1;" ::: "memory");
        } else {
            asm volatile("cp.async.wait_group 0;" ::: "memory");
        }
        __syncthreads();

        const uint32_t stage_b = smb + buf*STAGE_B;

        #pragma unroll
        for (int ks = 0; ks < 32; ks += 16){
            uint32_t bh[4][2], bl[4][2];
            #pragma unroll
            for (int p = 0; p < 2; p++){
                uint32_t ab = stage_b + 2*TEN_B + (b_elem[p] + ks)*2;
                LDSM4(bh[2*p][0], bh[2*p][1], bh[2*p+1][0], bh[2*p+1][1], ab);
                uint32_t al_ = stage_b + 3*TEN_B + (b_elem[p] + ks)*2;
                LDSM4(bl[2*p][0], bl[2*p][1], bl[2*p+1][0], bl[2*p+1][1], al_);
            }
            #pragma unroll
            for (int mi = 0; mi < 4; mi++){
                uint32_t ah[4], al[4];
                uint32_t aa = stage_b + (a_elem + mi*16*LDT + ks)*2;
                LDSM4(ah[0], ah[1], ah[2], ah[3], aa);
                uint32_t ab = stage_b + TEN_B + (a_elem + mi*16*LDT + ks)*2;
                LDSM4(al[0], al[1], al[2], al[3], ab);
                #pragma unroll
                for (int ni = 0; ni < 4; ni++){
                    MMA16816(acc[mi][ni], ah, bh[ni]);
                    MMA16816(acc[mi][ni], al, bh[ni]);
                    MMA16816(acc[mi][ni], ah, bl[ni]);
                }
            }
        }
        __syncthreads();
    }

    #pragma unroll
    for (int mi = 0; mi < 4; mi++){
        long long r = row0 + wm*64 + mi*16 + g;
        #pragma unroll
        for (int ni = 0; ni < 4; ni++){
            long long cc = col0 + wn*32 + ni*8 + c2;
            float b0 = bias[cc], b1 = bias[cc + 1];
            float2 v0, v1;
            v0.x = acc[mi][ni][0] + b0; v0.y = acc[mi][ni][1] + b1;
            v1.x = acc[mi][ni][2] + b0; v1.y = acc[mi][ni][3] + b1;
            *(float2*)(C + r*V_ + cc)       = v0;
            *(float2*)(C + (r + 8)*V_ + cc) = v1;
        }
    }
}

// ---------------- launch -----------------------------------------------------
extern "C" void kernel_launch(void* const* d_in, const int* in_sizes, int n_in,
                              void* d_out, int out_size){
    const int*   y     = (const int*)  d_in[0];
    const float* h0    = (const float*)d_in[1];
    const float* c0    = (const float*)d_in[2];
    const float* enc   = (const float*)d_in[3];
    const float* emb   = (const float*)d_in[4];
    const float* Wx    = (const float*)d_in[5];
    const float* Wh    = (const float*)d_in[6];
    const float* bvec  = (const float*)d_in[7];
    const float* Wk    = (const float*)d_in[8];
    const float* Wq    = (const float*)d_in[9];
    const float* v_att = (const float*)d_in[10];
    const float* Wa    = (const float*)d_in[11];
    const float* Wout  = (const float*)d_in[12];
    const float* bout  = (const float*)d_in[13];
    float* out = (float*)d_out;

    void* p;
    cudaGetSymbolAddress(&p, g_keys); float* keys_p = (float*)p;

    cudaFuncSetAttribute(gemm_mma, cudaFuncAttributeMaxDynamicSharedMemorySize, GM_SMEM);
    cudaFuncSetAttribute(step_persist, cudaFuncAttributeMaxDynamicSharedMemorySize, PS_SMEM);

    init_hc<<<128, 256>>>(h0, c0);
    embed_gather<<<B_*T_, 128>>>(y, emb);
    reset_sync<<<1, 1>>>();

    // Wout bf16 split+transpose (independent of the loop)
    split_wout<<<dim3(V_/32, U_/32), 256>>>(Wout);

    // keys = enc @ Wk (must precede persistent kernel's attention phase)
    sgemm128<<<dim3((B_*S_)/128, U_/128), 256>>>(enc, Wk, nullptr, keys_p,
                                                 B_*S_, U_, U_);

    // all 64 recurrence steps in one persistent kernel (emits Ah/Al directly)
    step_persist<<<NBLK, 512, PS_SMEM>>>(Wx, Wh, bvec, Wq, enc, v_att, Wa);

    // tensor-core output GEMM
    gemm_mma<<<dim3((B_*T_)/128, V_/128), 256, GM_SMEM>>>(bout, out);
}

// round 15
// speedup vs baseline: 1.6534x; 1.6534x over previous
#include <cuda_runtime.h>
#include <cuda_bf16.h>
#include <math.h>
#include <stdint.h>

#define B_ 32
#define T_ 64
#define S_ 64
#define V_ 32000
#define E_ 512
#define U_ 1024

// ---------------- scratch (static device globals; no allocs) ----------------
__device__ float g_keys [B_*S_*U_];
__device__ float g_zpart[5*B_*4*U_];      // z split-k partials (5 x 512k chunks)
__device__ float g_qpart[16*B_*U_];
__device__ float g_apart[16*B_*U_];
__device__ float g_h    [B_*U_];
__device__ float g_c    [B_*U_];
__device__ float g_ctx  [B_*U_];
// bf16 hi/lo operands
__device__ __nv_bfloat16 g_embh[B_*T_*E_], g_embl[B_*T_*E_];   // decoder inputs
__device__ __nv_bfloat16 g_aph [B_*U_],    g_apl [B_*U_];      // a(t-1) split
__device__ __nv_bfloat16 g_hh  [B_*U_],    g_hl  [B_*U_];      // h split
__device__ __nv_bfloat16 g_WxTh[4096*1536], g_WxTl[4096*1536]; // Wx^T n-major
__device__ __nv_bfloat16 g_WhTh[4096*1024], g_WhTl[4096*1024]; // Wh^T n-major
__device__ __nv_bfloat16 g_Ah[B_*T_*U_],   g_Al[B_*T_*U_];     // attn rows split
__device__ __nv_bfloat16 g_Bh[V_*U_],      g_Bl[V_*U_];        // Wout^T split

__device__ __forceinline__ float tanh_fast(float x){
    float r; asm("tanh.approx.f32 %0, %1;" : "=f"(r) : "f"(x)); return r;
}
__device__ __forceinline__ float sigmoid_acc(float x){
    return 1.0f / (1.0f + expf(-x));
}

// ---- packed f32x2 helpers ----
__device__ __forceinline__ unsigned long long pack2(float a, float b){
    unsigned long long r;
    asm("mov.b64 %0, {%1, %2};" : "=l"(r) : "f"(a), "f"(b));
    return r;
}
__device__ __forceinline__ void unpack2(unsigned long long v, float& a, float& b){
    asm("mov.b64 {%0, %1}, %2;" : "=f"(a), "=f"(b) : "l"(v));
}
#define FMA2(acc, x, w) \
    asm("fma.rn.f32x2 %0, %1, %2, %0;" : "+l"(acc) : "l"(x), "l"(w))

// ---- mma / ldmatrix / cp.async primitives (proven in gemm_mma) ----
#define MMA16816(c, a, b) \
    asm volatile("mma.sync.aligned.m16n8k16.row.col.f32.bf16.bf16.f32 " \
        "{%0,%1,%2,%3}, {%4,%5,%6,%7}, {%8,%9}, {%0,%1,%2,%3};" \
        : "+f"((c)[0]), "+f"((c)[1]), "+f"((c)[2]), "+f"((c)[3]) \
        : "r"((a)[0]), "r"((a)[1]), "r"((a)[2]), "r"((a)[3]), \
          "r"((b)[0]), "r"((b)[1]))

#define LDSM4(R0, R1, R2, R3, ADDR) \
    asm volatile("ldmatrix.sync.aligned.m8n8.x4.shared.b16 {%0,%1,%2,%3}, [%4];" \
        : "=r"(R0), "=r"(R1), "=r"(R2), "=r"(R3) : "r"(ADDR))

#define CPASYNC16(dst, src) \
    asm volatile("cp.async.cg.shared.global [%0], [%1], 16;" \
        :: "r"(dst), "l"(src) : "memory")

// ---------------- init h/c (+ h bf16 split) ----------------
__global__ void init_hc(const float* __restrict__ h0, const float* __restrict__ c0){
    int i = blockIdx.x * blockDim.x + threadIdx.x;
    if (i < B_*U_){
        float h = h0[i];
        g_h[i] = h; g_c[i] = c0[i];
        __nv_bfloat16 hh = __float2bfloat16(h);
        g_hh[i] = hh;
        g_hl[i] = __float2bfloat16(h - __bfloat162float(hh));
    }
}

// ---------------- embedding gather -> bf16 hi/lo ----------------
__global__ void embed_gather(const int* __restrict__ y, const float* __restrict__ emb){
    int bt = blockIdx.x;
    int b = bt / T_, t = bt % T_;
    int tok = (t == 0) ? 1 : y[b*T_ + t - 1];
    int i = threadIdx.x;                      // 128 threads, E/4
    float4 v = ((const float4*)(emb + (long long)tok * E_))[i];
    long long o = (long long)bt*E_ + i*4;
    float vv[4] = {v.x, v.y, v.z, v.w};
    #pragma unroll
    for (int q = 0; q < 4; q++){
        __nv_bfloat16 h = __float2bfloat16(vv[q]);
        g_embh[o+q] = h;
        g_embl[o+q] = __float2bfloat16(vv[q] - __bfloat162float(h));
    }
}

// ---------------- generic bf16 split + transpose: W[K][N] -> out[N][K] -----
__global__ __launch_bounds__(256)
void split_wT(const float* __restrict__ W, __nv_bfloat16* __restrict__ oh,
              __nv_bfloat16* __restrict__ ol, int K, int N){
    __shared__ float s[32][33];
    int n0 = blockIdx.x * 32, k0 = blockIdx.y * 32;
    int tx = threadIdx.x & 31, ty = threadIdx.x >> 5;
    #pragma unroll
    for (int i = 0; i < 32; i += 8)
        s[ty+i][tx] = W[(long long)(k0+ty+i)*N + n0 + tx];
    __syncthreads();
    #pragma unroll
    for (int i = 0; i < 32; i += 8){
        int n = ty + i;
        float a = s[tx][n];
        __nv_bfloat16 h = __float2bfloat16(a);
        long long o = (long long)(n0+n)*K + k0 + tx;
        oh[o] = h;
        ol[o] = __float2bfloat16(a - __bfloat162float(h));
    }
}

// ---------------- prep: reduce attnout partials -> a(t-1) hi/lo ------------
__global__ void prep_step(int t){
    int b = blockIdx.x;
    for (int u = threadIdx.x; u < U_; u += 256){
        if (t == 0){
            g_aph[b*U_ + u] = __float2bfloat16(0.0f);
            g_apl[b*U_ + u] = __float2bfloat16(0.0f);
        } else {
            float s = 0.0f;
            #pragma unroll
            for (int p = 0; p < 16; p++)
                s += g_apart[((long long)p*B_ + b)*U_ + u];
            __nv_bfloat16 h = __float2bfloat16(s);
            __nv_bfloat16 l = __float2bfloat16(s - __bfloat162float(h));
            long long o = ((long long)b*T_ + (t-1))*U_ + u;
            g_Ah[o] = h; g_Al[o] = l;
            if (t < T_){ g_aph[b*U_ + u] = h; g_apl[b*U_ + u] = l; }
        }
    }
}

// ---------------- z via tensor cores: z = [emb;aprev]@Wx + h@Wh ------------
// grid (64 nb, 5 kc), 128 threads. Block: M32 x N64 x K512, bf16 2-way split.
#define ZLD   72
#define ZA_SZ (32*ZLD)                 // 2304 elems
#define ZB_SZ (64*ZLD)                 // 4608 elems
#define ZBUF  (2*ZA_SZ + 2*ZB_SZ)      // 13824 elems per buffer
#define Z_SMEM (2*ZBUF*2)              // 55296 bytes

__global__ __launch_bounds__(128)
void z_mma(int t){
    extern __shared__ __nv_bfloat16 zs[];
    const int tid = threadIdx.x, lane = tid & 31, wid = tid >> 5;
    const int nb = blockIdx.x, kc = blockIdx.y;
    const int n0 = nb * 64;

    const __nv_bfloat16 *Ahg, *Alg, *Bhg, *Blg;
    long long astr, bstr;
    if (kc == 0){
        Ahg = g_embh + (long long)t*E_;  Alg = g_embl + (long long)t*E_;
        astr = (long long)T_*E_;
        Bhg = g_WxTh + (long long)n0*1536; Blg = g_WxTl + (long long)n0*1536;
        bstr = 1536;
    } else if (kc < 3){
        int off = (kc-1)*512;
        Ahg = g_aph + off; Alg = g_apl + off; astr = U_;
        Bhg = g_WxTh + (long long)n0*1536 + 512 + off;
        Blg = g_WxTl + (long long)n0*1536 + 512 + off;
        bstr = 1536;
    } else {
        int off = (kc-3)*512;
        Ahg = g_hh + off; Alg = g_hl + off; astr = U_;
        Bhg = g_WhTh + (long long)n0*1024 + off;
        Blg = g_WhTl + (long long)n0*1024 + off;
        bstr = 1024;
    }

    const uint32_t smb = (uint32_t)__cvta_generic_to_shared(zs);
    const uint32_t a_elem = (uint32_t)((((lane>>3)&1)*8 + (lane&7))*ZLD + (lane>>4)*8);
    const uint32_t b_elem = (uint32_t)((wid*16 + (lane>>4)*8 + (lane&7))*ZLD + ((lane>>3)&1)*8);

    float acc[2][2][4];
    #pragma unroll
    for (int mi = 0; mi < 2; mi++)
        #pragma unroll
        for (int ni = 0; ni < 2; ni++)
            #pragma unroll
            for (int q = 0; q < 4; q++) acc[mi][ni][q] = 0.0f;

    auto issue = [&](int s, int buf){
        __nv_bfloat16* base = zs + buf*ZBUF;
        #pragma unroll
        for (int i = 0; i < 2; i++){                 // A: 256 x 16B per tensor
            int idx = i*128 + tid;
            int row = idx >> 3, seg = idx & 7;
            uint32_t d0 = (uint32_t)__cvta_generic_to_shared(base + row*ZLD + seg*8);
            CPASYNC16(d0, Ahg + (long long)row*astr + s*64 + seg*8);
            uint32_t d1 = (uint32_t)__cvta_generic_to_shared(base + ZA_SZ + row*ZLD + seg*8);
            CPASYNC16(d1, Alg + (long long)row*astr + s*64 + seg*8);
        }
        #pragma unroll
        for (int i = 0; i < 4; i++){                 // B: 512 x 16B per tensor
            int idx = i*128 + tid;
            int row = idx >> 3, seg = idx & 7;
            uint32_t d0 = (uint32_t)__cvta_generic_to_shared(base + 2*ZA_SZ + row*ZLD + seg*8);
            CPASYNC16(d0, Bhg + (long long)row*bstr + s*64 + seg*8);
            uint32_t d1 = (uint32_t)__cvta_generic_to_shared(base + 2*ZA_SZ + ZB_SZ + row*ZLD + seg*8);
            CPASYNC16(d1, Blg + (long long)row*bstr + s*64 + seg*8);
        }
        asm volatile("cp.async.commit_group;" ::: "memory");
    };

    issue(0, 0);
    for (int s = 0; s < 8; s++){
        int buf = s & 1;
        if (s + 1 < 8){
            issue(s + 1, buf ^ 1);
            asm volatile("cp.async.wait_group 1;" ::: "memory");
        } else {
            asm volatile("cp.async.wait_group 0;" ::: "memory");
        }
        __syncthreads();

        const uint32_t bb = smb + buf*ZBUF*2;
        #pragma unroll
        for (int ks = 0; ks < 64; ks += 16){
            uint32_t bhf[2][2], blf[2][2];
            LDSM4(bhf[0][0], bhf[0][1], bhf[1][0], bhf[1][1],
                  bb + (2*ZA_SZ)*2 + (b_elem + ks)*2);
            LDSM4(blf[0][0], blf[0][1], blf[1][0], blf[1][1],
                  bb + (2*ZA_SZ + ZB_SZ)*2 + (b_elem + ks)*2);
            #pragma unroll
            for (int mi = 0; mi < 2; mi++){
                uint32_t ahf[4], alf[4];
                LDSM4(ahf[0], ahf[1], ahf[2], ahf[3],
                      bb + (a_elem + mi*16*ZLD + ks)*2);
                LDSM4(alf[0], alf[1], alf[2], alf[3],
                      bb + ZA_SZ*2 + (a_elem + mi*16*ZLD + ks)*2);
                #pragma unroll
                for (int ni = 0; ni < 2; ni++){
                    MMA16816(acc[mi][ni], ahf, bhf[ni]);
                    MMA16816(acc[mi][ni], alf, bhf[ni]);
                    MMA16816(acc[mi][ni], ahf, blf[ni]);
                }
            }
        }
        __syncthreads();
    }

    // epilogue: write fp32 partials
    int g = lane >> 2, c2 = (lane & 3) * 2;
    #pragma unroll
    for (int mi = 0; mi < 2; mi++){
        #pragma unroll
        for (int ni = 0; ni < 2; ni++){
            int b = mi*16 + g;
            int n = n0 + wid*16 + ni*8 + c2;
            float2 v0 = {acc[mi][ni][0], acc[mi][ni][1]};
            float2 v1 = {acc[mi][ni][2], acc[mi][ni][3]};
            *(float2*)(g_zpart + ((long long)kc*B_ + b  )*4096 + n) = v0;
            *(float2*)(g_zpart + ((long long)kc*B_ + b+8)*4096 + n) = v1;
        }
    }
}

// ---------------- LSTM pointwise: reduce 5 z-partials, split h -------------
__global__ void lstm_pt(const float* __restrict__ bias){
    int idx = blockIdx.x * blockDim.x + threadIdx.x;
    if (idx >= B_*U_) return;
    int b = idx >> 10, u = idx & 1023;
    float zi = bias[u], zj = bias[U_+u], zf = bias[2*U_+u], zo = bias[3*U_+u];
    #pragma unroll
    for (int p = 0; p < 5; p++){
        const float* zp = g_zpart + ((long long)p*B_ + b)*4096;
        zi += zp[u]; zj += zp[U_+u]; zf += zp[2*U_+u]; zo += zp[3*U_+u];
    }
    float c  = g_c[idx];
    float cn = sigmoid_acc(zf + 1.0f) * c + sigmoid_acc(zi) * tanhf(zj);
    float hn = sigmoid_acc(zo) * tanhf(cn);
    g_c[idx] = cn;
    g_h[idx] = hn;
    __nv_bfloat16 hh = __float2bfloat16(hn);
    g_hh[idx] = hh;
    g_hl[idx] = __float2bfloat16(hn - __bfloat162float(hh));
}

// ---------------- q split-k partial (f32x2, unchanged from R12) ------------
__global__ __launch_bounds__(128)
void q_partial(const float* __restrict__ Wq){
    __shared__ float xs[64][36];
    int tid = threadIdx.x;
    int kb  = blockIdx.y;
    int j   = blockIdx.x * 128 + tid;
    int r0  = kb * 64;

    int b = tid >> 2, kq = tid & 3;
    #pragma unroll
    for (int i = 0; i < 4; i++){
        int k = kq*16 + i*4;
        float4 v = *(const float4*)(g_h + b*U_ + r0 + k);
        xs[k+0][b] = v.x; xs[k+1][b] = v.y; xs[k+2][b] = v.z; xs[k+3][b] = v.w;
    }
    __syncthreads();

    unsigned long long acc2[16];
    #pragma unroll
    for (int i = 0; i < 16; i++) acc2[i] = 0ull;

    const float* w = Wq + (long long)r0*U_ + j;
    #pragma unroll 4
    for (int k = 0; k < 64; k += 4){
        float w0 = w[(long long)(k+0)*U_];
        float w1 = w[(long long)(k+1)*U_];
        float w2 = w[(long long)(k+2)*U_];
        float w3 = w[(long long)(k+3)*U_];
        #pragma unroll
        for (int kk = 0; kk < 4; kk++){
            float wk = (kk==0)?w0:(kk==1)?w1:(kk==2)?w2:w3;
            unsigned long long wk2 = pack2(wk, wk);
            #pragma unroll
            for (int b4 = 0; b4 < 8; b4++){
                float4 xv = *(const float4*)&xs[k+kk][b4*4];
                unsigned long long x01 = pack2(xv.x, xv.y);
                unsigned long long x23 = pack2(xv.z, xv.w);
                FMA2(acc2[b4*2+0], x01, wk2);
                FMA2(acc2[b4*2+1], x23, wk2);
            }
        }
    }
    #pragma unroll
    for (int p = 0; p < 16; p++){
        float v0, v1; unpack2(acc2[p], v0, v1);
        g_qpart[((long long)kb*B_ + 2*p+0)*U_ + j] = v0;
        g_qpart[((long long)kb*B_ + 2*p+1)*U_ + j] = v1;
    }
}

// ---------------- scores + softmax + context (unchanged) -------------------
__global__ __launch_bounds__(512)
void attn_step(const float* __restrict__ enc, const float* __restrict__ v){
    int b = blockIdx.x;
    __shared__ float q_s[U_];
    __shared__ float sc_s[S_];
    __shared__ float al_s[S_];
    int tid = threadIdx.x;

    for (int u = tid; u < U_; u += 512){
        float s = 0.0f;
        #pragma unroll
        for (int p = 0; p < 16; p++)
            s += g_qpart[((long long)p*B_ + b)*U_ + u];
        q_s[u] = s;
    }
    __syncthreads();

    int warp = tid >> 5, lane = tid & 31;
    #pragma unroll
    for (int si = 0; si < 4; si++){
        int s = warp*4 + si;
        const float* kp = g_keys + (long long)(b*S_ + s)*U_;
        float p = 0.f;
        for (int u = lane; u < U_; u += 32)
            p = fmaf(tanh_fast(kp[u] + q_s[u]), v[u], p);
        #pragma unroll
        for (int off = 16; off; off >>= 1)
            p += __shfl_xor_sync(0xffffffffu, p, off);
        if (lane == 0) sc_s[s] = p;
    }
    __syncthreads();

    if (warp == 0){
        float s0 = sc_s[lane], s1 = sc_s[lane+32];
        float m = fmaxf(s0, s1);
        #pragma unroll
        for (int off = 16; off; off >>= 1)
            m = fmaxf(m, __shfl_xor_sync(0xffffffffu, m, off));
        float e0 = expf(s0 - m), e1 = expf(s1 - m);
        float sum = e0 + e1;
        #pragma unroll
        for (int off = 16; off; off >>= 1)
            sum += __shfl_xor_sync(0xffffffffu, sum, off);
        float inv = 1.0f / sum;
        al_s[lane]    = e0 * inv;
        al_s[lane+32] = e1 * inv;
    }
    __syncthreads();

    for (int e = tid; e < U_; e += 512){
        const float* ep = enc + (long long)b*S_*U_ + e;
        float a = 0.f;
        #pragma unroll 16
        for (int s = 0; s < S_; s++)
            a = fmaf(al_s[s], ep[(long long)s*U_], a);
        g_ctx[(long long)b*U_ + e] = a;
    }
}

// ---------------- attnout split-k partial (f32x2, unchanged) ---------------
__global__ __launch_bounds__(128)
void attnout_partial(const float* __restrict__ Wa){
    __shared__ float xs[128][36];
    int tid = threadIdx.x;
    int kb  = blockIdx.y;
    int j   = blockIdx.x * 128 + tid;

    const float* xp = (kb < 8) ? (g_h + kb*128) : (g_ctx + (kb-8)*128);
    const float* wp = Wa + (long long)(kb*128)*U_;

    int b = tid >> 2, kq = tid & 3;
    #pragma unroll
    for (int i = 0; i < 8; i++){
        int k = kq*32 + i*4;
        float4 v = *(const float4*)(xp + b*U_ + k);
        xs[k+0][b] = v.x; xs[k+1][b] = v.y; xs[k+2][b] = v.z; xs[k+3][b] = v.w;
    }
    __syncthreads();

    unsigned long long acc2[16];
    #pragma unroll
    for (int i = 0; i < 16; i++) acc2[i] = 0ull;

    const float* w = wp + j;
    #pragma unroll 4
    for (int k = 0; k < 128; k += 4){
        float w0 = w[(long long)(k+0)*U_];
        float w1 = w[(long long)(k+1)*U_];
        float w2 = w[(long long)(k+2)*U_];
        float w3 = w[(long long)(k+3)*U_];
        #pragma unroll
        for (int kk = 0; kk < 4; kk++){
            float wk = (kk==0)?w0:(kk==1)?w1:(kk==2)?w2:w3;
            unsigned long long wk2 = pack2(wk, wk);
            #pragma unroll
            for (int b4 = 0; b4 < 8; b4++){
                float4 xv = *(const float4*)&xs[k+kk][b4*4];
                unsigned long long x01 = pack2(xv.x, xv.y);
                unsigned long long x23 = pack2(xv.z, xv.w);
                FMA2(acc2[b4*2+0], x01, wk2);
                FMA2(acc2[b4*2+1], x23, wk2);
            }
        }
    }
    #pragma unroll
    for (int p = 0; p < 16; p++){
        float v0, v1; unpack2(acc2[p], v0, v1);
        g_apart[((long long)kb*B_ + 2*p+0)*U_ + j] = v0;
        g_apart[((long long)kb*B_ + 2*p+1)*U_ + j] = v1;
    }
}

// ---------------- fp32 SGEMM (keys only, f32x2) ----------------
__global__ __launch_bounds__(256)
void sgemm128(const float* __restrict__ A, const float* __restrict__ Bm,
              const float* __restrict__ bias, float* __restrict__ C,
              int M, int N, int K){
    __shared__ float As[16][132];
    __shared__ float Bs[16][132];
    int tid = threadIdx.x;
    int tx = tid & 15, ty = tid >> 4;
    int row0 = blockIdx.x * 128, col0 = blockIdx.y * 128;

    int m0 = tid >> 2, kq = tid & 3;
    int kr = tid >> 5, n4 = tid & 31;

    unsigned long long acc2[8][4];
    #pragma unroll
    for (int i = 0; i < 8; i++)
        #pragma unroll
        for (int j = 0; j < 4; j++) acc2[i][j] = 0ull;

    const float* Ap  = A  + (long long)(row0 + m0)*K + kq*4;
    const float* Ap2 = Ap + (long long)64*K;
    const float* Bp  = Bm + (long long)kr*N + col0 + n4*4;
    const float* Bp2 = Bp + (long long)8*N;

    float4 pa0 = *(const float4*)Ap;
    float4 pa1 = *(const float4*)Ap2;
    float4 pb0 = *(const float4*)Bp;
    float4 pb1 = *(const float4*)Bp2;

    int nk = K >> 4;
    for (int kt = 0; kt < nk; kt++){
        As[kq*4+0][m0]    = pa0.x; As[kq*4+1][m0]    = pa0.y;
        As[kq*4+2][m0]    = pa0.z; As[kq*4+3][m0]    = pa0.w;
        As[kq*4+0][m0+64] = pa1.x; As[kq*4+1][m0+64] = pa1.y;
        As[kq*4+2][m0+64] = pa1.z; As[kq*4+3][m0+64] = pa1.w;
        *(float4*)&Bs[kr][n4*4]   = pb0;
        *(float4*)&Bs[kr+8][n4*4] = pb1;
        __syncthreads();

        if (kt + 1 < nk){
            pa0 = *(const float4*)(Ap  + (kt+1)*16);
            pa1 = *(const float4*)(Ap2 + (kt+1)*16);
            pb0 = *(const float4*)(Bp  + (long long)(kt+1)*16*N);
            pb1 = *(const float4*)(Bp2 + (long long)(kt+1)*16*N);
        }

        #pragma unroll
        for (int k = 0; k < 16; k++){
            float a[8];
            *(float4*)&a[0]  = *(const float4*)&As[k][ty*8];
            *(float4*)&a[4]  = *(const float4*)&As[k][ty*8+4];
            float4 b0 = *(const float4*)&Bs[k][tx*8];
            float4 b1 = *(const float4*)&Bs[k][tx*8+4];
            unsigned long long bb2[4];
            bb2[0] = pack2(b0.x, b0.y); bb2[1] = pack2(b0.z, b0.w);
            bb2[2] = pack2(b1.x, b1.y); bb2[3] = pack2(b1.z, b1.w);
            #pragma unroll
            for (int i = 0; i < 8; i++){
                unsigned long long ai = pack2(a[i], a[i]);
                #pragma unroll
                for (int j = 0; j < 4; j++)
                    FMA2(acc2[i][j], bb2[j], ai);
            }
        }
        __syncthreads();
    }

    float bv[8];
    #pragma unroll
    for (int j = 0; j < 8; j++) bv[j] = bias ? bias[col0 + tx*8 + j] : 0.0f;

    #pragma unroll
    for (int i = 0; i < 8; i++){
        float* cp = C + (long long)(row0 + ty*8 + i)*N + col0 + tx*8;
        float o[8];
        #pragma unroll
        for (int j = 0; j < 4; j++) unpack2(acc2[i][j], o[2*j], o[2*j+1]);
        float4 o0, o1;
        o0.x = o[0]+bv[0]; o0.y = o[1]+bv[1]; o0.z = o[2]+bv[2]; o0.w = o[3]+bv[3];
        o1.x = o[4]+bv[4]; o1.y = o[5]+bv[5]; o1.z = o[6]+bv[6]; o1.w = o[7]+bv[7];
        *(float4*)cp       = o0;
        *(float4*)(cp + 4) = o1;
    }
}

// ================= tensor-core output GEMM (unchanged from R12) ============
#define LDT     40
#define TEN     (128*LDT)
#define TEN_B   (TEN*2)
#define STAGE   (4*TEN)
#define STAGE_B (STAGE*2)
#define GM_SMEM (2*STAGE_B)

__global__ __launch_bounds__(256)
void gemm_mma(const float* __restrict__ bias, float* __restrict__ C){
    extern __shared__ __nv_bfloat16 sm[];
    const int tid  = threadIdx.x;
    const int lane = tid & 31, wid = tid >> 5;
    const int wm   = wid >> 2, wn = wid & 3;
    const int g    = lane >> 2, c2 = (lane & 3) * 2;
    const long long row0 = (long long)blockIdx.x * 128;
    const long long col0 = (long long)blockIdx.y * 128;

    const uint32_t smb = (uint32_t)__cvta_generic_to_shared(sm);

    const uint32_t a_elem = (uint32_t)(wm*64 + ((lane>>3)&1)*8 + (lane&7)) * LDT
                          + (uint32_t)((lane>>4)*8);
    uint32_t b_elem[2];
    #pragma unroll
    for (int p = 0; p < 2; p++)
        b_elem[p] = (uint32_t)(wn*32 + p*16 + (lane>>4)*8 + (lane&7)) * LDT
                  + (uint32_t)(((lane>>3)&1)*8);

    const int lr = tid >> 1;
    const int lc = (tid & 1) * 16;
    const __nv_bfloat16* srcs[4] = {
        g_Ah + (row0 + lr)*U_, g_Al + (row0 + lr)*U_,
        g_Bh + (col0 + lr)*U_, g_Bl + (col0 + lr)*U_ };

    float acc[4][4][4];
    #pragma unroll
    for (int mi = 0; mi < 4; mi++)
        #pragma unroll
        for (int ni = 0; ni < 4; ni++)
            #pragma unroll
            for (int q = 0; q < 4; q++) acc[mi][ni][q] = 0.0f;

    auto issue = [&](int kt, int buf){
        __nv_bfloat16* st = sm + buf*STAGE;
        #pragma unroll
        for (int tn = 0; tn < 4; tn++){
            uint32_t d = (uint32_t)__cvta_generic_to_shared(st + tn*TEN + lr*LDT + lc);
            const __nv_bfloat16* s = srcs[tn] + kt*32 + lc;
            asm volatile(
                "cp.async.cg.shared.global [%0], [%1], 16;\n\t"
                "cp.async.cg.shared.global [%2], [%3], 16;"
                :: "r"(d), "l"(s), "r"(d + 16), "l"(s + 8) : "memory");
        }
        asm volatile("cp.async.commit_group;" ::: "memory");
    };

    issue(0, 0);
    for (int kt = 0; kt < 32; kt++){
        int buf = kt & 1;
        if (kt + 1 < 32){
            issue(kt + 1, buf ^ 1);
            asm volatile("cp.async.wait_group 1;" ::: "memory");
        } else {
            asm volatile("cp.async.wait_group 0;" ::: "memory");
        }
        __syncthreads();

        const uint32_t stage_b = smb + buf*STAGE_B;

        #pragma unroll
        for (int ks = 0; ks < 32; ks += 16){
            uint32_t bh[4][2], bl[4][2];
            #pragma unroll
            for (int p = 0; p < 2; p++){
                uint32_t ab = stage_b + 2*TEN_B + (b_elem[p] + ks)*2;
                LDSM4(bh[2*p][0], bh[2*p][1], bh[2*p+1][0], bh[2*p+1][1], ab);
                uint32_t al_ = stage_b + 3*TEN_B + (b_elem[p] + ks)*2;
                LDSM4(bl[2*p][0], bl[2*p][1], bl[2*p+1][0], bl[2*p+1][1], al_);
            }
            #pragma unroll
            for (int mi = 0; mi < 4; mi++){
                uint32_t ah[4], al[4];
                uint32_t aa = stage_b + (a_elem + mi*16*LDT + ks)*2;
                LDSM4(ah[0], ah[1], ah[2], ah[3], aa);
                uint32_t ab = stage_b + TEN_B + (a_elem + mi*16*LDT + ks)*2;
                LDSM4(al[0], al[1], al[2], al[3], ab);
                #pragma unroll
                for (int ni = 0; ni < 4; ni++){
                    MMA16816(acc[mi][ni], ah, bh[ni]);
                    MMA16816(acc[mi][ni], al, bh[ni]);
                    MMA16816(acc[mi][ni], ah, bl[ni]);
                }
            }
        }
        __syncthreads();
    }

    #pragma unroll
    for (int mi = 0; mi < 4; mi++){
        long long r = row0 + wm*64 + mi*16 + g;
        #pragma unroll
        for (int ni = 0; ni < 4; ni++){
            long long cc = col0 + wn*32 + ni*8 + c2;
            float b0 = bias[cc], b1 = bias[cc + 1];
            float2 v0, v1;
            v0.x = acc[mi][ni][0] + b0; v0.y = acc[mi][ni][1] + b1;
            v1.x = acc[mi][ni][2] + b0; v1.y = acc[mi][ni][3] + b1;
            *(float2*)(C + r*V_ + cc)       = v0;
            *(float2*)(C + (r + 8)*V_ + cc) = v1;
        }
    }
}

// ---------------- launch -----------------------------------------------------
extern "C" void kernel_launch(void* const* d_in, const int* in_sizes, int n_in,
                              void* d_out, int out_size){
    const int*   y     = (const int*)  d_in[0];
    const float* h0    = (const float*)d_in[1];
    const float* c0    = (const float*)d_in[2];
    const float* enc   = (const float*)d_in[3];
    const float* emb   = (const float*)d_in[4];
    const float* Wx    = (const float*)d_in[5];
    const float* Wh    = (const float*)d_in[6];
    const float* bvec  = (const float*)d_in[7];
    const float* Wk    = (const float*)d_in[8];
    const float* Wq    = (const float*)d_in[9];
    const float* v_att = (const float*)d_in[10];
    const float* Wa    = (const float*)d_in[11];
    const float* Wout  = (const float*)d_in[12];
    const float* bout  = (const float*)d_in[13];
    float* out = (float*)d_out;

    void* p;
    cudaGetSymbolAddress(&p, g_keys); float* keys_p = (float*)p;
    __nv_bfloat16 *wxh, *wxl, *whh, *whl, *bh, *bl;
    cudaGetSymbolAddress(&p, g_WxTh); wxh = (__nv_bfloat16*)p;
    cudaGetSymbolAddress(&p, g_WxTl); wxl = (__nv_bfloat16*)p;
    cudaGetSymbolAddress(&p, g_WhTh); whh = (__nv_bfloat16*)p;
    cudaGetSymbolAddress(&p, g_WhTl); whl = (__nv_bfloat16*)p;
    cudaGetSymbolAddress(&p, g_Bh);   bh  = (__nv_bfloat16*)p;
    cudaGetSymbolAddress(&p, g_Bl);   bl  = (__nv_bfloat16*)p;

    cudaFuncSetAttribute(gemm_mma, cudaFuncAttributeMaxDynamicSharedMemorySize, GM_SMEM);
    cudaFuncSetAttribute(z_mma,    cudaFuncAttributeMaxDynamicSharedMemorySize, Z_SMEM);

    init_hc<<<128, 256>>>(h0, c0);
    embed_gather<<<B_*T_, 128>>>(y, emb);

    // one-time weight splits (n-major bf16 hi/lo)
    split_wT<<<dim3(V_/32,  U_/32),   256>>>(Wout, bh,  bl,  U_,  V_);
    split_wT<<<dim3(4096/32, 1536/32), 256>>>(Wx,  wxh, wxl, 1536, 4096);
    split_wT<<<dim3(4096/32, 1024/32), 256>>>(Wh,  whh, whl, 1024, 4096);

    // keys = enc @ Wk
    sgemm128<<<dim3((B_*S_)/128, U_/128), 256>>>(enc, Wk, nullptr, keys_p,
                                                 B_*S_, U_, U_);

    for (int t = 0; t < T_; t++){
        prep_step<<<32, 256>>>(t);
        z_mma<<<dim3(64, 5), 128, Z_SMEM>>>(t);
        lstm_pt<<<128, 256>>>(bvec);
        q_partial<<<dim3(8, 16), 128>>>(Wq);
        attn_step<<<32, 512>>>(enc, v_att);
        attnout_partial<<<dim3(8, 16), 128>>>(Wa);
    }
    prep_step<<<32, 256>>>(T_);   // emit Ah/Al for t = 63

    // tensor-core output GEMM
    gemm_mma<<<dim3((B_*T_)/128, V_/128), 256, GM_SMEM>>>(bout, out);
}

// round 16
// speedup vs baseline: 1.8320x; 1.1081x over previous
#include <cuda_runtime.h>
#include <cuda_bf16.h>
#include <math.h>
#include <stdint.h>

#define B_ 32
#define T_ 64
#define S_ 64
#define V_ 32000
#define E_ 512
#define U_ 1024

// ---------------- scratch (static device globals; no allocs) ----------------
__device__ float g_keys [B_*S_*U_];
__device__ float g_zpart[5*B_*4*U_];      // z split-k partials (5 x 512k)
__device__ float g_qpart[4*B_*U_];        // q partials (4 x 256k)
__device__ float g_apart[8*B_*U_];        // attnout partials (8 x 256k)
__device__ float g_c    [B_*U_];
// bf16 hi/lo operands
__device__ __nv_bfloat16 g_embh[B_*T_*E_], g_embl[B_*T_*E_];
__device__ __nv_bfloat16 g_aph [B_*U_],    g_apl [B_*U_];
__device__ __nv_bfloat16 g_hh  [B_*U_],    g_hl  [B_*U_];
__device__ __nv_bfloat16 g_ctxh[B_*U_],    g_ctxl[B_*U_];
__device__ __nv_bfloat16 g_WxTh[4096*1536], g_WxTl[4096*1536];
__device__ __nv_bfloat16 g_WhTh[4096*1024], g_WhTl[4096*1024];
__device__ __nv_bfloat16 g_WqTh[1024*1024], g_WqTl[1024*1024];
__device__ __nv_bfloat16 g_WaTh[1024*2048], g_WaTl[1024*2048];
__device__ __nv_bfloat16 g_Ah[B_*T_*U_],   g_Al[B_*T_*U_];
__device__ __nv_bfloat16 g_Bh[V_*U_],      g_Bl[V_*U_];

__device__ __forceinline__ float tanh_fast(float x){
    float r; asm("tanh.approx.f32 %0, %1;" : "=f"(r) : "f"(x)); return r;
}
__device__ __forceinline__ float sigmoid_acc(float x){
    return 1.0f / (1.0f + expf(-x));
}

// ---- packed f32x2 helpers (keys sgemm) ----
__device__ __forceinline__ unsigned long long pack2(float a, float b){
    unsigned long long r;
    asm("mov.b64 %0, {%1, %2};" : "=l"(r) : "f"(a), "f"(b));
    return r;
}
__device__ __forceinline__ void unpack2(unsigned long long v, float& a, float& b){
    asm("mov.b64 {%0, %1}, %2;" : "=f"(a), "=f"(b) : "l"(v));
}
#define FMA2(acc, x, w) \
    asm("fma.rn.f32x2 %0, %1, %2, %0;" : "+l"(acc) : "l"(x), "l"(w))

// ---- mma / ldmatrix / cp.async primitives ----
#define MMA16816(c, a, b) \
    asm volatile("mma.sync.aligned.m16n8k16.row.col.f32.bf16.bf16.f32 " \
        "{%0,%1,%2,%3}, {%4,%5,%6,%7}, {%8,%9}, {%0,%1,%2,%3};" \
        : "+f"((c)[0]), "+f"((c)[1]), "+f"((c)[2]), "+f"((c)[3]) \
        : "r"((a)[0]), "r"((a)[1]), "r"((a)[2]), "r"((a)[3]), \
          "r"((b)[0]), "r"((b)[1]))

#define LDSM4(R0, R1, R2, R3, ADDR) \
    asm volatile("ldmatrix.sync.aligned.m8n8.x4.shared.b16 {%0,%1,%2,%3}, [%4];" \
        : "=r"(R0), "=r"(R1), "=r"(R2), "=r"(R3) : "r"(ADDR))

#define CPASYNC16(dst, src) \
    asm volatile("cp.async.cg.shared.global [%0], [%1], 16;" \
        :: "r"(dst), "l"(src) : "memory")

// ---------------- init h/c (+ h bf16 split) ----------------
__global__ void init_hc(const float* __restrict__ h0, const float* __restrict__ c0){
    int i = blockIdx.x * blockDim.x + threadIdx.x;
    if (i < B_*U_){
        float h = h0[i];
        g_c[i] = c0[i];
        __nv_bfloat16 hh = __float2bfloat16(h);
        g_hh[i] = hh;
        g_hl[i] = __float2bfloat16(h - __bfloat162float(hh));
    }
}

// ---------------- embedding gather -> bf16 hi/lo ----------------
__global__ void embed_gather(const int* __restrict__ y, const float* __restrict__ emb){
    int bt = blockIdx.x;
    int b = bt / T_, t = bt % T_;
    int tok = (t == 0) ? 1 : y[b*T_ + t - 1];
    int i = threadIdx.x;
    float4 v = ((const float4*)(emb + (long long)tok * E_))[i];
    long long o = (long long)bt*E_ + i*4;
    float vv[4] = {v.x, v.y, v.z, v.w};
    #pragma unroll
    for (int q = 0; q < 4; q++){
        __nv_bfloat16 h = __float2bfloat16(vv[q]);
        g_embh[o+q] = h;
        g_embl[o+q] = __float2bfloat16(vv[q] - __bfloat162float(h));
    }
}

// ---------------- generic bf16 split + transpose: W[K][N] -> out[N][K] -----
__global__ __launch_bounds__(256)
void split_wT(const float* __restrict__ W, __nv_bfloat16* __restrict__ oh,
              __nv_bfloat16* __restrict__ ol, int K, int N){
    __shared__ float s[32][33];
    int n0 = blockIdx.x * 32, k0 = blockIdx.y * 32;
    int tx = threadIdx.x & 31, ty = threadIdx.x >> 5;
    #pragma unroll
    for (int i = 0; i < 32; i += 8)
        s[ty+i][tx] = W[(long long)(k0+ty+i)*N + n0 + tx];
    __syncthreads();
    #pragma unroll
    for (int i = 0; i < 32; i += 8){
        int n = ty + i;
        float a = s[tx][n];
        __nv_bfloat16 h = __float2bfloat16(a);
        long long o = (long long)(n0+n)*K + k0 + tx;
        oh[o] = h;
        ol[o] = __float2bfloat16(a - __bfloat162float(h));
    }
}

// ---------------- prep: reduce attnout partials -> a(t-1) hi/lo ------------
__global__ void prep_step(int t){
    int b = blockIdx.x;
    for (int u = threadIdx.x; u < U_; u += 256){
        if (t == 0){
            g_aph[b*U_ + u] = __float2bfloat16(0.0f);
            g_apl[b*U_ + u] = __float2bfloat16(0.0f);
        } else {
            float s = 0.0f;
            #pragma unroll
            for (int p = 0; p < 8; p++)
                s += g_apart[((long long)p*B_ + b)*U_ + u];
            __nv_bfloat16 h = __float2bfloat16(s);
            __nv_bfloat16 l = __float2bfloat16(s - __bfloat162float(h));
            long long o = ((long long)b*T_ + (t-1))*U_ + u;
            g_Ah[o] = h; g_Al[o] = l;
            if (t < T_){ g_aph[b*U_ + u] = h; g_apl[b*U_ + u] = l; }
        }
    }
}

// ========== generic bf16-split MMA body: M32 x N64 x K(NSLICE*64) ==========
#define ZLD   72
#define ZA_SZ (32*ZLD)
#define ZB_SZ (64*ZLD)
#define ZBUF  (2*ZA_SZ + 2*ZB_SZ)      // 13824 elems per buffer
#define Z_SMEM (2*ZBUF*2)              // 55296 bytes

template<int NSLICE>
__device__ __forceinline__ void rec_mma_body(__nv_bfloat16* zs, int tid,
        const __nv_bfloat16* __restrict__ Ahg, const __nv_bfloat16* __restrict__ Alg,
        long long astr,
        const __nv_bfloat16* __restrict__ Bhg, const __nv_bfloat16* __restrict__ Blg,
        long long bstr,
        float* __restrict__ outp, int ostride){
    const int lane = tid & 31, wid = tid >> 5;
    const uint32_t smb = (uint32_t)__cvta_generic_to_shared(zs);
    const uint32_t a_elem = (uint32_t)((((lane>>3)&1)*8 + (lane&7))*ZLD + (lane>>4)*8);
    const uint32_t b_elem = (uint32_t)((wid*16 + (lane>>4)*8 + (lane&7))*ZLD + ((lane>>3)&1)*8);

    float acc[2][2][4];
    #pragma unroll
    for (int mi = 0; mi < 2; mi++)
        #pragma unroll
        for (int ni = 0; ni < 2; ni++)
            #pragma unroll
            for (int q = 0; q < 4; q++) acc[mi][ni][q] = 0.0f;

    auto issue = [&](int s, int buf){
        __nv_bfloat16* base = zs + buf*ZBUF;
        #pragma unroll
        for (int i = 0; i < 2; i++){
            int idx = i*128 + tid;
            int row = idx >> 3, seg = idx & 7;
            uint32_t d0 = (uint32_t)__cvta_generic_to_shared(base + row*ZLD + seg*8);
            CPASYNC16(d0, Ahg + (long long)row*astr + s*64 + seg*8);
            uint32_t d1 = (uint32_t)__cvta_generic_to_shared(base + ZA_SZ + row*ZLD + seg*8);
            CPASYNC16(d1, Alg + (long long)row*astr + s*64 + seg*8);
        }
        #pragma unroll
        for (int i = 0; i < 4; i++){
            int idx = i*128 + tid;
            int row = idx >> 3, seg = idx & 7;
            uint32_t d0 = (uint32_t)__cvta_generic_to_shared(base + 2*ZA_SZ + row*ZLD + seg*8);
            CPASYNC16(d0, Bhg + (long long)row*bstr + s*64 + seg*8);
            uint32_t d1 = (uint32_t)__cvta_generic_to_shared(base + 2*ZA_SZ + ZB_SZ + row*ZLD + seg*8);
            CPASYNC16(d1, Blg + (long long)row*bstr + s*64 + seg*8);
        }
        asm volatile("cp.async.commit_group;" ::: "memory");
    };

    issue(0, 0);
    for (int s = 0; s < NSLICE; s++){
        int buf = s & 1;
        if (s + 1 < NSLICE){
            issue(s + 1, buf ^ 1);
            asm volatile("cp.async.wait_group 1;" ::: "memory");
        } else {
            asm volatile("cp.async.wait_group 0;" ::: "memory");
        }
        __syncthreads();

        const uint32_t bb = smb + buf*ZBUF*2;
        #pragma unroll
        for (int ks = 0; ks < 64; ks += 16){
            uint32_t bhf[2][2], blf[2][2];
            LDSM4(bhf[0][0], bhf[0][1], bhf[1][0], bhf[1][1],
                  bb + (2*ZA_SZ)*2 + (b_elem + ks)*2);
            LDSM4(blf[0][0], blf[0][1], blf[1][0], blf[1][1],
                  bb + (2*ZA_SZ + ZB_SZ)*2 + (b_elem + ks)*2);
            #pragma unroll
            for (int mi = 0; mi < 2; mi++){
                uint32_t ahf[4], alf[4];
                LDSM4(ahf[0], ahf[1], ahf[2], ahf[3],
                      bb + (a_elem + mi*16*ZLD + ks)*2);
                LDSM4(alf[0], alf[1], alf[2], alf[3],
                      bb + ZA_SZ*2 + (a_elem + mi*16*ZLD + ks)*2);
                #pragma unroll
                for (int ni = 0; ni < 2; ni++){
                    MMA16816(acc[mi][ni], ahf, bhf[ni]);
                    MMA16816(acc[mi][ni], alf, bhf[ni]);
                    MMA16816(acc[mi][ni], ahf, blf[ni]);
                }
            }
        }
        __syncthreads();
    }

    int g = lane >> 2, c2 = (lane & 3) * 2;
    #pragma unroll
    for (int mi = 0; mi < 2; mi++){
        #pragma unroll
        for (int ni = 0; ni < 2; ni++){
            int b = mi*16 + g;
            int n = wid*16 + ni*8 + c2;
            float2 v0 = {acc[mi][ni][0], acc[mi][ni][1]};
            float2 v1 = {acc[mi][ni][2], acc[mi][ni][3]};
            *(float2*)(outp + (long long)(b  )*ostride + n) = v0;
            *(float2*)(outp + (long long)(b+8)*ostride + n) = v1;
        }
    }
}

// ---------------- z: grid (64 nb, 5 kc), K512 chunks ----------------
__global__ __launch_bounds__(128)
void z_mma(int t){
    extern __shared__ __nv_bfloat16 zs[];
    const int nb = blockIdx.x, kc = blockIdx.y;
    const int n0 = nb * 64;

    const __nv_bfloat16 *Ahg, *Alg, *Bhg, *Blg;
    long long astr, bstr;
    if (kc == 0){
        Ahg = g_embh + (long long)t*E_;  Alg = g_embl + (long long)t*E_;
        astr = (long long)T_*E_;
        Bhg = g_WxTh + (long long)n0*1536; Blg = g_WxTl + (long long)n0*1536;
        bstr = 1536;
    } else if (kc < 3){
        int off = (kc-1)*512;
        Ahg = g_aph + off; Alg = g_apl + off; astr = U_;
        Bhg = g_WxTh + (long long)n0*1536 + 512 + off;
        Blg = g_WxTl + (long long)n0*1536 + 512 + off;
        bstr = 1536;
    } else {
        int off = (kc-3)*512;
        Ahg = g_hh + off; Alg = g_hl + off; astr = U_;
        Bhg = g_WhTh + (long long)n0*1024 + off;
        Blg = g_WhTl + (long long)n0*1024 + off;
        bstr = 1024;
    }
    rec_mma_body<8>(zs, threadIdx.x, Ahg, Alg, astr, Bhg, Blg, bstr,
                    g_zpart + (long long)kc*B_*4096 + n0, 4096);
}

// ---------------- q: grid (16 nb, 4 kc), K256 chunks of h ----------------
__global__ __launch_bounds__(128)
void q_mma(){
    extern __shared__ __nv_bfloat16 zs[];
    const int nb = blockIdx.x, kc = blockIdx.y;
    const int n0 = nb * 64;
    int off = kc * 256;
    rec_mma_body<4>(zs, threadIdx.x,
                    g_hh + off, g_hl + off, U_,
                    g_WqTh + (long long)n0*1024 + off,
                    g_WqTl + (long long)n0*1024 + off, 1024,
                    g_qpart + (long long)kc*B_*U_ + n0, U_);
}

// ---------------- attnout: grid (16 nb, 8 kc), K256 chunks of [h;ctx] ------
__global__ __launch_bounds__(128)
void o_mma(){
    extern __shared__ __nv_bfloat16 zs[];
    const int nb = blockIdx.x, kc = blockIdx.y;
    const int n0 = nb * 64;
    int off = kc * 256;
    const __nv_bfloat16* Ahg = (kc < 4) ? (g_hh + off) : (g_ctxh + off - 1024);
    const __nv_bfloat16* Alg = (kc < 4) ? (g_hl + off) : (g_ctxl + off - 1024);
    rec_mma_body<4>(zs, threadIdx.x, Ahg, Alg, U_,
                    g_WaTh + (long long)n0*2048 + off,
                    g_WaTl + (long long)n0*2048 + off, 2048,
                    g_apart + (long long)kc*B_*U_ + n0, U_);
}

// ---------------- LSTM pointwise: reduce 5 z-partials, split h -------------
__global__ void lstm_pt(const float* __restrict__ bias){
    int idx = blockIdx.x * blockDim.x + threadIdx.x;
    if (idx >= B_*U_) return;
    int b = idx >> 10, u = idx & 1023;
    float zi = bias[u], zj = bias[U_+u], zf = bias[2*U_+u], zo = bias[3*U_+u];
    #pragma unroll
    for (int p = 0; p < 5; p++){
        const float* zp = g_zpart + ((long long)p*B_ + b)*4096;
        zi += zp[u]; zj += zp[U_+u]; zf += zp[2*U_+u]; zo += zp[3*U_+u];
    }
    float c  = g_c[idx];
    float cn = sigmoid_acc(zf + 1.0f) * c + sigmoid_acc(zi) * tanhf(zj);
    float hn = sigmoid_acc(zo) * tanhf(cn);
    g_c[idx] = cn;
    __nv_bfloat16 hh = __float2bfloat16(hn);
    g_hh[idx] = hh;
    g_hl[idx] = __float2bfloat16(hn - __bfloat162float(hh));
}

// ---------------- scores + softmax + context -> ctx hi/lo ------------------
__global__ __launch_bounds__(512)
void attn_step(const float* __restrict__ enc, const float* __restrict__ v){
    int b = blockIdx.x;
    __shared__ float q_s[U_];
    __shared__ float sc_s[S_];
    __shared__ float al_s[S_];
    int tid = threadIdx.x;

    for (int u = tid; u < U_; u += 512){
        float s = 0.0f;
        #pragma unroll
        for (int p = 0; p < 4; p++)
            s += g_qpart[((long long)p*B_ + b)*U_ + u];
        q_s[u] = s;
    }
    __syncthreads();

    int warp = tid >> 5, lane = tid & 31;
    #pragma unroll
    for (int si = 0; si < 4; si++){
        int s = warp*4 + si;
        const float* kp = g_keys + (long long)(b*S_ + s)*U_;
        float p = 0.f;
        for (int u = lane; u < U_; u += 32)
            p = fmaf(tanh_fast(kp[u] + q_s[u]), v[u], p);
        #pragma unroll
        for (int off = 16; off; off >>= 1)
            p += __shfl_xor_sync(0xffffffffu, p, off);
        if (lane == 0) sc_s[s] = p;
    }
    __syncthreads();

    if (warp == 0){
        float s0 = sc_s[lane], s1 = sc_s[lane+32];
        float m = fmaxf(s0, s1);
        #pragma unroll
        for (int off = 16; off; off >>= 1)
            m = fmaxf(m, __shfl_xor_sync(0xffffffffu, m, off));
        float e0 = expf(s0 - m), e1 = expf(s1 - m);
        float sum = e0 + e1;
        #pragma unroll
        for (int off = 16; off; off >>= 1)
            sum += __shfl_xor_sync(0xffffffffu, sum, off);
        float inv = 1.0f / sum;
        al_s[lane]    = e0 * inv;
        al_s[lane+32] = e1 * inv;
    }
    __syncthreads();

    for (int e = tid; e < U_; e += 512){
        const float* ep = enc + (long long)b*S_*U_ + e;
        float a = 0.f;
        #pragma unroll 16
        for (int s = 0; s < S_; s++)
            a = fmaf(al_s[s], ep[(long long)s*U_], a);
        __nv_bfloat16 h = __float2bfloat16(a);
        g_ctxh[(long long)b*U_ + e] = h;
        g_ctxl[(long long)b*U_ + e] = __float2bfloat16(a - __bfloat162float(h));
    }
}

// ---------------- fp32 SGEMM (keys only, f32x2) ----------------
__global__ __launch_bounds__(256)
void sgemm128(const float* __restrict__ A, const float* __restrict__ Bm,
              const float* __restrict__ bias, float* __restrict__ C,
              int M, int N, int K){
    __shared__ float As[16][132];
    __shared__ float Bs[16][132];
    int tid = threadIdx.x;
    int tx = tid & 15, ty = tid >> 4;
    int row0 = blockIdx.x * 128, col0 = blockIdx.y * 128;

    int m0 = tid >> 2, kq = tid & 3;
    int kr = tid >> 5, n4 = tid & 31;

    unsigned long long acc2[8][4];
    #pragma unroll
    for (int i = 0; i < 8; i++)
        #pragma unroll
        for (int j = 0; j < 4; j++) acc2[i][j] = 0ull;

    const float* Ap  = A  + (long long)(row0 + m0)*K + kq*4;
    const float* Ap2 = Ap + (long long)64*K;
    const float* Bp  = Bm + (long long)kr*N + col0 + n4*4;
    const float* Bp2 = Bp + (long long)8*N;

    float4 pa0 = *(const float4*)Ap;
    float4 pa1 = *(const float4*)Ap2;
    float4 pb0 = *(const float4*)Bp;
    float4 pb1 = *(const float4*)Bp2;

    int nk = K >> 4;
    for (int kt = 0; kt < nk; kt++){
        As[kq*4+0][m0]    = pa0.x; As[kq*4+1][m0]    = pa0.y;
        As[kq*4+2][m0]    = pa0.z; As[kq*4+3][m0]    = pa0.w;
        As[kq*4+0][m0+64] = pa1.x; As[kq*4+1][m0+64] = pa1.y;
        As[kq*4+2][m0+64] = pa1.z; As[kq*4+3][m0+64] = pa1.w;
        *(float4*)&Bs[kr][n4*4]   = pb0;
        *(float4*)&Bs[kr+8][n4*4] = pb1;
        __syncthreads();

        if (kt + 1 < nk){
            pa0 = *(const float4*)(Ap  + (kt+1)*16);
            pa1 = *(const float4*)(Ap2 + (kt+1)*16);
            pb0 = *(const float4*)(Bp  + (long long)(kt+1)*16*N);
            pb1 = *(const float4*)(Bp2 + (long long)(kt+1)*16*N);
        }

        #pragma unroll
        for (int k = 0; k < 16; k++){
            float a[8];
            *(float4*)&a[0]  = *(const float4*)&As[k][ty*8];
            *(float4*)&a[4]  = *(const float4*)&As[k][ty*8+4];
            float4 b0 = *(const float4*)&Bs[k][tx*8];
            float4 b1 = *(const float4*)&Bs[k][tx*8+4];
            unsigned long long bb2[4];
            bb2[0] = pack2(b0.x, b0.y); bb2[1] = pack2(b0.z, b0.w);
            bb2[2] = pack2(b1.x, b1.y); bb2[3] = pack2(b1.z, b1.w);
            #pragma unroll
            for (int i = 0; i < 8; i++){
                unsigned long long ai = pack2(a[i], a[i]);
                #pragma unroll
                for (int j = 0; j < 4; j++)
                    FMA2(acc2[i][j], bb2[j], ai);
            }
        }
        __syncthreads();
    }

    float bv[8];
    #pragma unroll
    for (int j = 0; j < 8; j++) bv[j] = bias ? bias[col0 + tx*8 + j] : 0.0f;

    #pragma unroll
    for (int i = 0; i < 8; i++){
        float* cp = C + (long long)(row0 + ty*8 + i)*N + col0 + tx*8;
        float o[8];
        #pragma unroll
        for (int j = 0; j < 4; j++) unpack2(acc2[i][j], o[2*j], o[2*j+1]);
        float4 o0, o1;
        o0.x = o[0]+bv[0]; o0.y = o[1]+bv[1]; o0.z = o[2]+bv[2]; o0.w = o[3]+bv[3];
        o1.x = o[4]+bv[4]; o1.y = o[5]+bv[5]; o1.z = o[6]+bv[6]; o1.w = o[7]+bv[7];
        *(float4*)cp       = o0;
        *(float4*)(cp + 4) = o1;
    }
}

// ================= tensor-core output GEMM (unchanged) =====================
#define LDT     40
#define TEN     (128*LDT)
#define TEN_B   (TEN*2)
#define STAGE   (4*TEN)
#define STAGE_B (STAGE*2)
#define GM_SMEM (2*STAGE_B)

__global__ __launch_bounds__(256)
void gemm_mma(const float* __restrict__ bias, float* __restrict__ C){
    extern __shared__ __nv_bfloat16 sm[];
    const int tid  = threadIdx.x;
    const int lane = tid & 31, wid = tid >> 5;
    const int wm   = wid >> 2, wn = wid & 3;
    const int g    = lane >> 2, c2 = (lane & 3) * 2;
    const long long row0 = (long long)blockIdx.x * 128;
    const long long col0 = (long long)blockIdx.y * 128;

    const uint32_t smb = (uint32_t)__cvta_generic_to_shared(sm);

    const uint32_t a_elem = (uint32_t)(wm*64 + ((lane>>3)&1)*8 + (lane&7)) * LDT
                          + (uint32_t)((lane>>4)*8);
    uint32_t b_elem[2];
    #pragma unroll
    for (int p = 0; p < 2; p++)
        b_elem[p] = (uint32_t)(wn*32 + p*16 + (lane>>4)*8 + (lane&7)) * LDT
                  + (uint32_t)(((lane>>3)&1)*8);

    const int lr = tid >> 1;
    const int lc = (tid & 1) * 16;
    const __nv_bfloat16* srcs[4] = {
        g_Ah + (row0 + lr)*U_, g_Al + (row0 + lr)*U_,
        g_Bh + (col0 + lr)*U_, g_Bl + (col0 + lr)*U_ };

    float acc[4][4][4];
    #pragma unroll
    for (int mi = 0; mi < 4; mi++)
        #pragma unroll
        for (int ni = 0; ni < 4; ni++)
            #pragma unroll
            for (int q = 0; q < 4; q++) acc[mi][ni][q] = 0.0f;

    auto issue = [&](int kt, int buf){
        __nv_bfloat16* st = sm + buf*STAGE;
        #pragma unroll
        for (int tn = 0; tn < 4; tn++){
            uint32_t d = (uint32_t)__cvta_generic_to_shared(st + tn*TEN + lr*LDT + lc);
            const __nv_bfloat16* s = srcs[tn] + kt*32 + lc;
            asm volatile(
                "cp.async.cg.shared.global [%0], [%1], 16;\n\t"
                "cp.async.cg.shared.global [%2], [%3], 16;"
                :: "r"(d), "l"(s), "r"(d + 16), "l"(s + 8) : "memory");
        }
        asm volatile("cp.async.commit_group;" ::: "memory");
    };

    issue(0, 0);
    for (int kt = 0; kt < 32; kt++){
        int buf = kt & 1;
        if (kt + 1 < 32){
            issue(kt + 1, buf ^ 1);
            asm volatile("cp.async.wait_group 1;" ::: "memory");
        } else {
            asm volatile("cp.async.wait_group 0;" ::: "memory");
        }
        __syncthreads();

        const uint32_t stage_b = smb + buf*STAGE_B;

        #pragma unroll
        for (int ks = 0; ks < 32; ks += 16){
            uint32_t bh[4][2], bl[4][2];
            #pragma unroll
            for (int p = 0; p < 2; p++){
                uint32_t ab = stage_b + 2*TEN_B + (b_elem[p] + ks)*2;
                LDSM4(bh[2*p][0], bh[2*p][1], bh[2*p+1][0], bh[2*p+1][1], ab);
                uint32_t al_ = stage_b + 3*TEN_B + (b_elem[p] + ks)*2;
                LDSM4(bl[2*p][0], bl[2*p][1], bl[2*p+1][0], bl[2*p+1][1], al_);
            }
            #pragma unroll
            for (int mi = 0; mi < 4; mi++){
                uint32_t ah[4], al[4];
                uint32_t aa = stage_b + (a_elem + mi*16*LDT + ks)*2;
                LDSM4(ah[0], ah[1], ah[2], ah[3], aa);
                uint32_t ab = stage_b + TEN_B + (a_elem + mi*16*LDT + ks)*2;
                LDSM4(al[0], al[1], al[2], al[3], ab);
                #pragma unroll
                for (int ni = 0; ni < 4; ni++){
                    MMA16816(acc[mi][ni], ah, bh[ni]);
                    MMA16816(acc[mi][ni], al, bh[ni]);
                    MMA16816(acc[mi][ni], ah, bl[ni]);
                }
            }
        }
        __syncthreads();
    }

    #pragma unroll
    for (int mi = 0; mi < 4; mi++){
        long long r = row0 + wm*64 + mi*16 + g;
        #pragma unroll
        for (int ni = 0; ni < 4; ni++){
            long long cc = col0 + wn*32 + ni*8 + c2;
            float b0 = bias[cc], b1 = bias[cc + 1];
            float2 v0, v1;
            v0.x = acc[mi][ni][0] + b0; v0.y = acc[mi][ni][1] + b1;
            v1.x = acc[mi][ni][2] + b0; v1.y = acc[mi][ni][3] + b1;
            *(float2*)(C + r*V_ + cc)       = v0;
            *(float2*)(C + (r + 8)*V_ + cc) = v1;
        }
    }
}

// ---------------- launch -----------------------------------------------------
extern "C" void kernel_launch(void* const* d_in, const int* in_sizes, int n_in,
                              void* d_out, int out_size){
    const int*   y     = (const int*)  d_in[0];
    const float* h0    = (const float*)d_in[1];
    const float* c0    = (const float*)d_in[2];
    const float* enc   = (const float*)d_in[3];
    const float* emb   = (const float*)d_in[4];
    const float* Wx    = (const float*)d_in[5];
    const float* Wh    = (const float*)d_in[6];
    const float* bvec  = (const float*)d_in[7];
    const float* Wk    = (const float*)d_in[8];
    const float* Wq    = (const float*)d_in[9];
    const float* v_att = (const float*)d_in[10];
    const float* Wa    = (const float*)d_in[11];
    const float* Wout  = (const float*)d_in[12];
    const float* bout  = (const float*)d_in[13];
    float* out = (float*)d_out;

    void* p;
    cudaGetSymbolAddress(&p, g_keys); float* keys_p = (float*)p;
    __nv_bfloat16 *wxh, *wxl, *whh, *whl, *wqh, *wql, *wah, *wal, *bh, *bl;
    cudaGetSymbolAddress(&p, g_WxTh); wxh = (__nv_bfloat16*)p;
    cudaGetSymbolAddress(&p, g_WxTl); wxl = (__nv_bfloat16*)p;
    cudaGetSymbolAddress(&p, g_WhTh); whh = (__nv_bfloat16*)p;
    cudaGetSymbolAddress(&p, g_WhTl); whl = (__nv_bfloat16*)p;
    cudaGetSymbolAddress(&p, g_WqTh); wqh = (__nv_bfloat16*)p;
    cudaGetSymbolAddress(&p, g_WqTl); wql = (__nv_bfloat16*)p;
    cudaGetSymbolAddress(&p, g_WaTh); wah = (__nv_bfloat16*)p;
    cudaGetSymbolAddress(&p, g_WaTl); wal = (__nv_bfloat16*)p;
    cudaGetSymbolAddress(&p, g_Bh);   bh  = (__nv_bfloat16*)p;
    cudaGetSymbolAddress(&p, g_Bl);   bl  = (__nv_bfloat16*)p;

    cudaFuncSetAttribute(gemm_mma, cudaFuncAttributeMaxDynamicSharedMemorySize, GM_SMEM);
    cudaFuncSetAttribute(z_mma, cudaFuncAttributeMaxDynamicSharedMemorySize, Z_SMEM);
    cudaFuncSetAttribute(q_mma, cudaFuncAttributeMaxDynamicSharedMemorySize, Z_SMEM);
    cudaFuncSetAttribute(o_mma, cudaFuncAttributeMaxDynamicSharedMemorySize, Z_SMEM);

    init_hc<<<128, 256>>>(h0, c0);
    embed_gather<<<B_*T_, 128>>>(y, emb);

    // one-time weight splits (n-major bf16 hi/lo)
    split_wT<<<dim3(V_/32,  U_/32),    256>>>(Wout, bh,  bl,  U_,   V_);
    split_wT<<<dim3(4096/32, 1536/32), 256>>>(Wx,   wxh, wxl, 1536, 4096);
    split_wT<<<dim3(4096/32, 1024/32), 256>>>(Wh,   whh, whl, 1024, 4096);
    split_wT<<<dim3(1024/32, 1024/32), 256>>>(Wq,   wqh, wql, 1024, 1024);
    split_wT<<<dim3(1024/32, 2048/32), 256>>>(Wa,   wah, wal, 2048, 1024);

    // keys = enc @ Wk
    sgemm128<<<dim3((B_*S_)/128, U_/128), 256>>>(enc, Wk, nullptr, keys_p,
                                                 B_*S_, U_, U_);

    for (int t = 0; t < T_; t++){
        prep_step<<<32, 256>>>(t);
        z_mma<<<dim3(64, 5), 128, Z_SMEM>>>(t);
        lstm_pt<<<128, 256>>>(bvec);
        q_mma<<<dim3(16, 4), 128, Z_SMEM>>>();
        attn_step<<<32, 512>>>(enc, v_att);
        o_mma<<<dim3(16, 8), 128, Z_SMEM>>>();
    }
    prep_step<<<32, 256>>>(T_);   // emit Ah/Al for t = 63

    // tensor-core output GEMM
    gemm_mma<<<dim3((B_*T_)/128, V_/128), 256, GM_SMEM>>>(bout, out);
}

// round 17
// speedup vs baseline: 1.8362x; 1.0023x over previous
#include <cuda_runtime.h>
#include <cuda_bf16.h>
#include <math.h>
#include <stdint.h>

#define B_ 32
#define T_ 64
#define S_ 64
#define V_ 32000
#define E_ 512
#define U_ 1024

// ---------------- scratch (static device globals; no allocs) ----------------
__device__ float g_keys [B_*S_*U_];
__device__ float g_zpart[5*B_*4*U_];
__device__ float g_qpart[4*B_*U_];
__device__ float g_apart[8*B_*U_];
__device__ float g_c    [B_*U_];
// bf16 hi/lo operands
__device__ __nv_bfloat16 g_embh[B_*T_*E_], g_embl[B_*T_*E_];
__device__ __nv_bfloat16 g_aph [B_*U_],    g_apl [B_*U_];
__device__ __nv_bfloat16 g_hh  [B_*U_],    g_hl  [B_*U_];
__device__ __nv_bfloat16 g_ctxh[B_*U_],    g_ctxl[B_*U_];
__device__ __nv_bfloat16 g_WxTh[4096*1536], g_WxTl[4096*1536];
__device__ __nv_bfloat16 g_WhTh[4096*1024], g_WhTl[4096*1024];
__device__ __nv_bfloat16 g_WqTh[1024*1024], g_WqTl[1024*1024];
__device__ __nv_bfloat16 g_WaTh[1024*2048], g_WaTl[1024*2048];
__device__ __nv_bfloat16 g_Ah[B_*T_*U_],   g_Al[B_*T_*U_];
__device__ __nv_bfloat16 g_Bh[V_*U_],      g_Bl[V_*U_];

__device__ __forceinline__ float tanh_fast(float x){
    float r; asm("tanh.approx.f32 %0, %1;" : "=f"(r) : "f"(x)); return r;
}
__device__ __forceinline__ float sigmoid_acc(float x){
    return 1.0f / (1.0f + expf(-x));
}

// ---- packed f32x2 helpers (keys sgemm) ----
__device__ __forceinline__ unsigned long long pack2(float a, float b){
    unsigned long long r;
    asm("mov.b64 %0, {%1, %2};" : "=l"(r) : "f"(a), "f"(b));
    return r;
}
__device__ __forceinline__ void unpack2(unsigned long long v, float& a, float& b){
    asm("mov.b64 {%0, %1}, %2;" : "=f"(a), "=f"(b) : "l"(v));
}
#define FMA2(acc, x, w) \
    asm("fma.rn.f32x2 %0, %1, %2, %0;" : "+l"(acc) : "l"(x), "l"(w))

// ---- mma / ldmatrix / cp.async primitives ----
#define MMA16816(c, a, b) \
    asm volatile("mma.sync.aligned.m16n8k16.row.col.f32.bf16.bf16.f32 " \
        "{%0,%1,%2,%3}, {%4,%5,%6,%7}, {%8,%9}, {%0,%1,%2,%3};" \
        : "+f"((c)[0]), "+f"((c)[1]), "+f"((c)[2]), "+f"((c)[3]) \
        : "r"((a)[0]), "r"((a)[1]), "r"((a)[2]), "r"((a)[3]), \
          "r"((b)[0]), "r"((b)[1]))

#define LDSM4(R0, R1, R2, R3, ADDR) \
    asm volatile("ldmatrix.sync.aligned.m8n8.x4.shared.b16 {%0,%1,%2,%3}, [%4];" \
        : "=r"(R0), "=r"(R1), "=r"(R2), "=r"(R3) : "r"(ADDR))

#define CPASYNC16(dst, src) \
    asm volatile("cp.async.cg.shared.global [%0], [%1], 16;" \
        :: "r"(dst), "l"(src) : "memory")

// ---------------- init h/c (+ h bf16 split) ----------------
__global__ void init_hc(const float* __restrict__ h0, const float* __restrict__ c0){
    int i = blockIdx.x * blockDim.x + threadIdx.x;
    if (i < B_*U_){
        float h = h0[i];
        g_c[i] = c0[i];
        __nv_bfloat16 hh = __float2bfloat16(h);
        g_hh[i] = hh;
        g_hl[i] = __float2bfloat16(h - __bfloat162float(hh));
    }
}

// ---------------- embedding gather -> bf16 hi/lo ----------------
__global__ void embed_gather(const int* __restrict__ y, const float* __restrict__ emb){
    int bt = blockIdx.x;
    int b = bt / T_, t = bt % T_;
    int tok = (t == 0) ? 1 : y[b*T_ + t - 1];
    int i = threadIdx.x;
    float4 v = ((const float4*)(emb + (long long)tok * E_))[i];
    long long o = (long long)bt*E_ + i*4;
    float vv[4] = {v.x, v.y, v.z, v.w};
    #pragma unroll
    for (int q = 0; q < 4; q++){
        __nv_bfloat16 h = __float2bfloat16(vv[q]);
        g_embh[o+q] = h;
        g_embl[o+q] = __float2bfloat16(vv[q] - __bfloat162float(h));
    }
}

// ---------------- generic bf16 split + transpose: W[K][N] -> out[N][K] -----
__global__ __launch_bounds__(256)
void split_wT(const float* __restrict__ W, __nv_bfloat16* __restrict__ oh,
              __nv_bfloat16* __restrict__ ol, int K, int N){
    __shared__ float s[32][33];
    int n0 = blockIdx.x * 32, k0 = blockIdx.y * 32;
    int tx = threadIdx.x & 31, ty = threadIdx.x >> 5;
    #pragma unroll
    for (int i = 0; i < 32; i += 8)
        s[ty+i][tx] = W[(long long)(k0+ty+i)*N + n0 + tx];
    __syncthreads();
    #pragma unroll
    for (int i = 0; i < 32; i += 8){
        int n = ty + i;
        float a = s[tx][n];
        __nv_bfloat16 h = __float2bfloat16(a);
        long long o = (long long)(n0+n)*K + k0 + tx;
        oh[o] = h;
        ol[o] = __float2bfloat16(a - __bfloat162float(h));
    }
}

// ---------------- prep: reduce attnout partials -> a(t-1) hi/lo ------------
__global__ void prep_step(int t){
    int b = blockIdx.x;
    for (int u = threadIdx.x; u < U_; u += 256){
        if (t == 0){
            g_aph[b*U_ + u] = __float2bfloat16(0.0f);
            g_apl[b*U_ + u] = __float2bfloat16(0.0f);
        } else {
            float s = 0.0f;
            #pragma unroll
            for (int p = 0; p < 8; p++)
                s += g_apart[((long long)p*B_ + b)*U_ + u];
            __nv_bfloat16 h = __float2bfloat16(s);
            __nv_bfloat16 l = __float2bfloat16(s - __bfloat162float(h));
            long long o = ((long long)b*T_ + (t-1))*U_ + u;
            g_Ah[o] = h; g_Al[o] = l;
            if (t < T_){ g_aph[b*U_ + u] = h; g_apl[b*U_ + u] = l; }
        }
    }
}

// ========== generic bf16-split MMA body: M32 x N64 x K(NSLICE*64) ==========
#define ZLD   72
#define ZA_SZ (32*ZLD)
#define ZB_SZ (64*ZLD)
#define ZBUF  (2*ZA_SZ + 2*ZB_SZ)
#define Z_SMEM (2*ZBUF*2)

template<int NSLICE>
__device__ __forceinline__ void rec_mma_body(__nv_bfloat16* zs, int tid,
        const __nv_bfloat16* __restrict__ Ahg, const __nv_bfloat16* __restrict__ Alg,
        long long astr,
        const __nv_bfloat16* __restrict__ Bhg, const __nv_bfloat16* __restrict__ Blg,
        long long bstr,
        float* __restrict__ outp, int ostride){
    const int lane = tid & 31, wid = tid >> 5;
    const uint32_t smb = (uint32_t)__cvta_generic_to_shared(zs);
    const uint32_t a_elem = (uint32_t)((((lane>>3)&1)*8 + (lane&7))*ZLD + (lane>>4)*8);
    const uint32_t b_elem = (uint32_t)((wid*16 + (lane>>4)*8 + (lane&7))*ZLD + ((lane>>3)&1)*8);

    float acc[2][2][4];
    #pragma unroll
    for (int mi = 0; mi < 2; mi++)
        #pragma unroll
        for (int ni = 0; ni < 2; ni++)
            #pragma unroll
            for (int q = 0; q < 4; q++) acc[mi][ni][q] = 0.0f;

    auto issue = [&](int s, int buf){
        __nv_bfloat16* base = zs + buf*ZBUF;
        #pragma unroll
        for (int i = 0; i < 2; i++){
            int idx = i*128 + tid;
            int row = idx >> 3, seg = idx & 7;
            uint32_t d0 = (uint32_t)__cvta_generic_to_shared(base + row*ZLD + seg*8);
            CPASYNC16(d0, Ahg + (long long)row*astr + s*64 + seg*8);
            uint32_t d1 = (uint32_t)__cvta_generic_to_shared(base + ZA_SZ + row*ZLD + seg*8);
            CPASYNC16(d1, Alg + (long long)row*astr + s*64 + seg*8);
        }
        #pragma unroll
        for (int i = 0; i < 4; i++){
            int idx = i*128 + tid;
            int row = idx >> 3, seg = idx & 7;
            uint32_t d0 = (uint32_t)__cvta_generic_to_shared(base + 2*ZA_SZ + row*ZLD + seg*8);
            CPASYNC16(d0, Bhg + (long long)row*bstr + s*64 + seg*8);
            uint32_t d1 = (uint32_t)__cvta_generic_to_shared(base + 2*ZA_SZ + ZB_SZ + row*ZLD + seg*8);
            CPASYNC16(d1, Blg + (long long)row*bstr + s*64 + seg*8);
        }
        asm volatile("cp.async.commit_group;" ::: "memory");
    };

    issue(0, 0);
    for (int s = 0; s < NSLICE; s++){
        int buf = s & 1;
        if (s + 1 < NSLICE){
            issue(s + 1, buf ^ 1);
            asm volatile("cp.async.wait_group 1;" ::: "memory");
        } else {
            asm volatile("cp.async.wait_group 0;" ::: "memory");
        }
        __syncthreads();

        const uint32_t bb = smb + buf*ZBUF*2;
        #pragma unroll
        for (int ks = 0; ks < 64; ks += 16){
            // load ALL fragments first
            uint32_t bhf[2][2], blf[2][2];
            LDSM4(bhf[0][0], bhf[0][1], bhf[1][0], bhf[1][1],
                  bb + (2*ZA_SZ)*2 + (b_elem + ks)*2);
            LDSM4(blf[0][0], blf[0][1], blf[1][0], blf[1][1],
                  bb + (2*ZA_SZ + ZB_SZ)*2 + (b_elem + ks)*2);
            uint32_t ahf[2][4], alf[2][4];
            #pragma unroll
            for (int mi = 0; mi < 2; mi++){
                LDSM4(ahf[mi][0], ahf[mi][1], ahf[mi][2], ahf[mi][3],
                      bb + (a_elem + mi*16*ZLD + ks)*2);
                LDSM4(alf[mi][0], alf[mi][1], alf[mi][2], alf[mi][3],
                      bb + ZA_SZ*2 + (a_elem + mi*16*ZLD + ks)*2);
            }
            // three combo passes; each acc revisited only after 4 indep MMAs
            #pragma unroll
            for (int mi = 0; mi < 2; mi++)
                #pragma unroll
                for (int ni = 0; ni < 2; ni++)
                    MMA16816(acc[mi][ni], ahf[mi], bhf[ni]);
            #pragma unroll
            for (int mi = 0; mi < 2; mi++)
                #pragma unroll
                for (int ni = 0; ni < 2; ni++)
                    MMA16816(acc[mi][ni], alf[mi], bhf[ni]);
            #pragma unroll
            for (int mi = 0; mi < 2; mi++)
                #pragma unroll
                for (int ni = 0; ni < 2; ni++)
                    MMA16816(acc[mi][ni], ahf[mi], blf[ni]);
        }
        __syncthreads();
    }

    int g = lane >> 2, c2 = (lane & 3) * 2;
    #pragma unroll
    for (int mi = 0; mi < 2; mi++){
        #pragma unroll
        for (int ni = 0; ni < 2; ni++){
            int b = mi*16 + g;
            int n = wid*16 + ni*8 + c2;
            float2 v0 = {acc[mi][ni][0], acc[mi][ni][1]};
            float2 v1 = {acc[mi][ni][2], acc[mi][ni][3]};
            *(float2*)(outp + (long long)(b  )*ostride + n) = v0;
            *(float2*)(outp + (long long)(b+8)*ostride + n) = v1;
        }
    }
}

// ---------------- z: grid (64 nb, 5 kc), K512 chunks ----------------
__global__ __launch_bounds__(128)
void z_mma(int t){
    extern __shared__ __nv_bfloat16 zs[];
    const int nb = blockIdx.x, kc = blockIdx.y;
    const int n0 = nb * 64;

    const __nv_bfloat16 *Ahg, *Alg, *Bhg, *Blg;
    long long astr, bstr;
    if (kc == 0){
        Ahg = g_embh + (long long)t*E_;  Alg = g_embl + (long long)t*E_;
        astr = (long long)T_*E_;
        Bhg = g_WxTh + (long long)n0*1536; Blg = g_WxTl + (long long)n0*1536;
        bstr = 1536;
    } else if (kc < 3){
        int off = (kc-1)*512;
        Ahg = g_aph + off; Alg = g_apl + off; astr = U_;
        Bhg = g_WxTh + (long long)n0*1536 + 512 + off;
        Blg = g_WxTl + (long long)n0*1536 + 512 + off;
        bstr = 1536;
    } else {
        int off = (kc-3)*512;
        Ahg = g_hh + off; Alg = g_hl + off; astr = U_;
        Bhg = g_WhTh + (long long)n0*1024 + off;
        Blg = g_WhTl + (long long)n0*1024 + off;
        bstr = 1024;
    }
    rec_mma_body<8>(zs, threadIdx.x, Ahg, Alg, astr, Bhg, Blg, bstr,
                    g_zpart + (long long)kc*B_*4096 + n0, 4096);
}

// ---------------- q: grid (16 nb, 4 kc), K256 chunks of h ----------------
__global__ __launch_bounds__(128)
void q_mma(){
    extern __shared__ __nv_bfloat16 zs[];
    const int nb = blockIdx.x, kc = blockIdx.y;
    const int n0 = nb * 64;
    int off = kc * 256;
    rec_mma_body<4>(zs, threadIdx.x,
                    g_hh + off, g_hl + off, U_,
                    g_WqTh + (long long)n0*1024 + off,
                    g_WqTl + (long long)n0*1024 + off, 1024,
                    g_qpart + (long long)kc*B_*U_ + n0, U_);
}

// ---------------- attnout: grid (16 nb, 8 kc), K256 chunks of [h;ctx] ------
__global__ __launch_bounds__(128)
void o_mma(){
    extern __shared__ __nv_bfloat16 zs[];
    const int nb = blockIdx.x, kc = blockIdx.y;
    const int n0 = nb * 64;
    int off = kc * 256;
    const __nv_bfloat16* Ahg = (kc < 4) ? (g_hh + off) : (g_ctxh + off - 1024);
    const __nv_bfloat16* Alg = (kc < 4) ? (g_hl + off) : (g_ctxl + off - 1024);
    rec_mma_body<4>(zs, threadIdx.x, Ahg, Alg, U_,
                    g_WaTh + (long long)n0*2048 + off,
                    g_WaTl + (long long)n0*2048 + off, 2048,
                    g_apart + (long long)kc*B_*U_ + n0, U_);
}

// ---------------- LSTM pointwise: reduce 5 z-partials, split h -------------
__global__ void lstm_pt(const float* __restrict__ bias){
    int idx = blockIdx.x * blockDim.x + threadIdx.x;
    if (idx >= B_*U_) return;
    int b = idx >> 10, u = idx & 1023;
    float zi = bias[u], zj = bias[U_+u], zf = bias[2*U_+u], zo = bias[3*U_+u];
    #pragma unroll
    for (int p = 0; p < 5; p++){
        const float* zp = g_zpart + ((long long)p*B_ + b)*4096;
        zi += zp[u]; zj += zp[U_+u]; zf += zp[2*U_+u]; zo += zp[3*U_+u];
    }
    float c  = g_c[idx];
    float cn = sigmoid_acc(zf + 1.0f) * c + sigmoid_acc(zi) * tanhf(zj);
    float hn = sigmoid_acc(zo) * tanhf(cn);
    g_c[idx] = cn;
    __nv_bfloat16 hh = __float2bfloat16(hn);
    g_hh[idx] = hh;
    g_hl[idx] = __float2bfloat16(hn - __bfloat162float(hh));
}

// ---------------- scores + softmax + context -> ctx hi/lo ------------------
__global__ __launch_bounds__(512)
void attn_step(const float* __restrict__ enc, const float* __restrict__ v){
    int b = blockIdx.x;
    __shared__ float q_s[U_];
    __shared__ float sc_s[S_];
    __shared__ float al_s[S_];
    int tid = threadIdx.x;

    for (int u = tid; u < U_; u += 512){
        float s = 0.0f;
        #pragma unroll
        for (int p = 0; p < 4; p++)
            s += g_qpart[((long long)p*B_ + b)*U_ + u];
        q_s[u] = s;
    }
    __syncthreads();

    int warp = tid >> 5, lane = tid & 31;
    #pragma unroll
    for (int si = 0; si < 4; si++){
        int s = warp*4 + si;
        const float* kp = g_keys + (long long)(b*S_ + s)*U_;
        float p = 0.f;
        for (int u = lane; u < U_; u += 32)
            p = fmaf(tanh_fast(kp[u] + q_s[u]), v[u], p);
        #pragma unroll
        for (int off = 16; off; off >>= 1)
            p += __shfl_xor_sync(0xffffffffu, p, off);
        if (lane == 0) sc_s[s] = p;
    }
    __syncthreads();

    if (warp == 0){
        float s0 = sc_s[lane], s1 = sc_s[lane+32];
        float m = fmaxf(s0, s1);
        #pragma unroll
        for (int off = 16; off; off >>= 1)
            m = fmaxf(m, __shfl_xor_sync(0xffffffffu, m, off));
        float e0 = expf(s0 - m), e1 = expf(s1 - m);
        float sum = e0 + e1;
        #pragma unroll
        for (int off = 16; off; off >>= 1)
            sum += __shfl_xor_sync(0xffffffffu, sum, off);
        float inv = 1.0f / sum;
        al_s[lane]    = e0 * inv;
        al_s[lane+32] = e1 * inv;
    }
    __syncthreads();

    for (int e = tid; e < U_; e += 512){
        const float* ep = enc + (long long)b*S_*U_ + e;
        float a = 0.f;
        #pragma unroll 16
        for (int s = 0; s < S_; s++)
            a = fmaf(al_s[s], ep[(long long)s*U_], a);
        __nv_bfloat16 h = __float2bfloat16(a);
        g_ctxh[(long long)b*U_ + e] = h;
        g_ctxl[(long long)b*U_ + e] = __float2bfloat16(a - __bfloat162float(h));
    }
}

// ---------------- fp32 SGEMM (keys only, f32x2) ----------------
__global__ __launch_bounds__(256)
void sgemm128(const float* __restrict__ A, const float* __restrict__ Bm,
              const float* __restrict__ bias, float* __restrict__ C,
              int M, int N, int K){
    __shared__ float As[16][132];
    __shared__ float Bs[16][132];
    int tid = threadIdx.x;
    int tx = tid & 15, ty = tid >> 4;
    int row0 = blockIdx.x * 128, col0 = blockIdx.y * 128;

    int m0 = tid >> 2, kq = tid & 3;
    int kr = tid >> 5, n4 = tid & 31;

    unsigned long long acc2[8][4];
    #pragma unroll
    for (int i = 0; i < 8; i++)
        #pragma unroll
        for (int j = 0; j < 4; j++) acc2[i][j] = 0ull;

    const float* Ap  = A  + (long long)(row0 + m0)*K + kq*4;
    const float* Ap2 = Ap + (long long)64*K;
    const float* Bp  = Bm + (long long)kr*N + col0 + n4*4;
    const float* Bp2 = Bp + (long long)8*N;

    float4 pa0 = *(const float4*)Ap;
    float4 pa1 = *(const float4*)Ap2;
    float4 pb0 = *(const float4*)Bp;
    float4 pb1 = *(const float4*)Bp2;

    int nk = K >> 4;
    for (int kt = 0; kt < nk; kt++){
        As[kq*4+0][m0]    = pa0.x; As[kq*4+1][m0]    = pa0.y;
        As[kq*4+2][m0]    = pa0.z; As[kq*4+3][m0]    = pa0.w;
        As[kq*4+0][m0+64] = pa1.x; As[kq*4+1][m0+64] = pa1.y;
        As[kq*4+2][m0+64] = pa1.z; As[kq*4+3][m0+64] = pa1.w;
        *(float4*)&Bs[kr][n4*4]   = pb0;
        *(float4*)&Bs[kr+8][n4*4] = pb1;
        __syncthreads();

        if (kt + 1 < nk){
            pa0 = *(const float4*)(Ap  + (kt+1)*16);
            pa1 = *(const float4*)(Ap2 + (kt+1)*16);
            pb0 = *(const float4*)(Bp  + (long long)(kt+1)*16*N);
            pb1 = *(const float4*)(Bp2 + (long long)(kt+1)*16*N);
        }

        #pragma unroll
        for (int k = 0; k < 16; k++){
            float a[8];
            *(float4*)&a[0]  = *(const float4*)&As[k][ty*8];
            *(float4*)&a[4]  = *(const float4*)&As[k][ty*8+4];
            float4 b0 = *(const float4*)&Bs[k][tx*8];
            float4 b1 = *(const float4*)&Bs[k][tx*8+4];
            unsigned long long bb2[4];
            bb2[0] = pack2(b0.x, b0.y); bb2[1] = pack2(b0.z, b0.w);
            bb2[2] = pack2(b1.x, b1.y); bb2[3] = pack2(b1.z, b1.w);
            #pragma unroll
            for (int i = 0; i < 8; i++){
                unsigned long long ai = pack2(a[i], a[i]);
                #pragma unroll
                for (int j = 0; j < 4; j++)
                    FMA2(acc2[i][j], bb2[j], ai);
            }
        }
        __syncthreads();
    }

    float bv[8];
    #pragma unroll
    for (int j = 0; j < 8; j++) bv[j] = bias ? bias[col0 + tx*8 + j] : 0.0f;

    #pragma unroll
    for (int i = 0; i < 8; i++){
        float* cp = C + (long long)(row0 + ty*8 + i)*N + col0 + tx*8;
        float o[8];
        #pragma unroll
        for (int j = 0; j < 4; j++) unpack2(acc2[i][j], o[2*j], o[2*j+1]);
        float4 o0, o1;
        o0.x = o[0]+bv[0]; o0.y = o[1]+bv[1]; o0.z = o[2]+bv[2]; o0.w = o[3]+bv[3];
        o1.x = o[4]+bv[4]; o1.y = o[5]+bv[5]; o1.z = o[6]+bv[6]; o1.w = o[7]+bv[7];
        *(float4*)cp       = o0;
        *(float4*)(cp + 4) = o1;
    }
}

// ================= tensor-core output GEMM (RAW-chain-free schedule) =======
#define LDT     40
#define TEN     (128*LDT)
#define TEN_B   (TEN*2)
#define STAGE   (4*TEN)
#define STAGE_B (STAGE*2)
#define GM_SMEM (2*STAGE_B)

__global__ __launch_bounds__(256)
void gemm_mma(const float* __restrict__ bias, float* __restrict__ C){
    extern __shared__ __nv_bfloat16 sm[];
    const int tid  = threadIdx.x;
    const int lane = tid & 31, wid = tid >> 5;
    const int wm   = wid >> 2, wn = wid & 3;
    const int g    = lane >> 2, c2 = (lane & 3) * 2;
    const long long row0 = (long long)blockIdx.x * 128;
    const long long col0 = (long long)blockIdx.y * 128;

    const uint32_t smb = (uint32_t)__cvta_generic_to_shared(sm);

    const uint32_t a_elem = (uint32_t)(wm*64 + ((lane>>3)&1)*8 + (lane&7)) * LDT
                          + (uint32_t)((lane>>4)*8);
    uint32_t b_elem[2];
    #pragma unroll
    for (int p = 0; p < 2; p++)
        b_elem[p] = (uint32_t)(wn*32 + p*16 + (lane>>4)*8 + (lane&7)) * LDT
                  + (uint32_t)(((lane>>3)&1)*8);

    const int lr = tid >> 1;
    const int lc = (tid & 1) * 16;
    const __nv_bfloat16* srcs[4] = {
        g_Ah + (row0 + lr)*U_, g_Al + (row0 + lr)*U_,
        g_Bh + (col0 + lr)*U_, g_Bl + (col0 + lr)*U_ };

    float acc[4][4][4];
    #pragma unroll
    for (int mi = 0; mi < 4; mi++)
        #pragma unroll
        for (int ni = 0; ni < 4; ni++)
            #pragma unroll
            for (int q = 0; q < 4; q++) acc[mi][ni][q] = 0.0f;

    auto issue = [&](int kt, int buf){
        __nv_bfloat16* st = sm + buf*STAGE;
        #pragma unroll
        for (int tn = 0; tn < 4; tn++){
            uint32_t d = (uint32_t)__cvta_generic_to_shared(st + tn*TEN + lr*LDT + lc);
            const __nv_bfloat16* s = srcs[tn] + kt*32 + lc;
            asm volatile(
                "cp.async.cg.shared.global [%0], [%1], 16;\n\t"
                "cp.async.cg.shared.global [%2], [%3], 16;"
                :: "r"(d), "l"(s), "r"(d + 16), "l"(s + 8) : "memory");
        }
        asm volatile("cp.async.commit_group;" ::: "memory");
    };

    issue(0, 0);
    for (int kt = 0; kt < 32; kt++){
        int buf = kt & 1;
        if (kt + 1 < 32){
            issue(kt + 1, buf ^ 1);
            asm volatile("cp.async.wait_group 1;" ::: "memory");
        } else {
            asm volatile("cp.async.wait_group 0;" ::: "memory");
        }
        __syncthreads();

        const uint32_t stage_b = smb + buf*STAGE_B;

        #pragma unroll
        for (int ks = 0; ks < 32; ks += 16){
            // load ALL fragments for this k16 step
            uint32_t bh[4][2], bl[4][2];
            #pragma unroll
            for (int p = 0; p < 2; p++){
                uint32_t ab = stage_b + 2*TEN_B + (b_elem[p] + ks)*2;
                LDSM4(bh[2*p][0], bh[2*p][1], bh[2*p+1][0], bh[2*p+1][1], ab);
                uint32_t al_ = stage_b + 3*TEN_B + (b_elem[p] + ks)*2;
                LDSM4(bl[2*p][0], bl[2*p][1], bl[2*p+1][0], bl[2*p+1][1], al_);
            }
            uint32_t ah[4][4], al[4][4];
            #pragma unroll
            for (int mi = 0; mi < 4; mi++){
                uint32_t aa = stage_b + (a_elem + mi*16*LDT + ks)*2;
                LDSM4(ah[mi][0], ah[mi][1], ah[mi][2], ah[mi][3], aa);
                uint32_t ab = stage_b + TEN_B + (a_elem + mi*16*LDT + ks)*2;
                LDSM4(al[mi][0], al[mi][1], al[mi][2], al[mi][3], ab);
            }
            // three combo passes: each acc revisited after 16 indep MMAs
            #pragma unroll
            for (int mi = 0; mi < 4; mi++)
                #pragma unroll
                for (int ni = 0; ni < 4; ni++)
                    MMA16816(acc[mi][ni], ah[mi], bh[ni]);
            #pragma unroll
            for (int mi = 0; mi < 4; mi++)
                #pragma unroll
                for (int ni = 0; ni < 4; ni++)
                    MMA16816(acc[mi][ni], al[mi], bh[ni]);
            #pragma unroll
            for (int mi = 0; mi < 4; mi++)
                #pragma unroll
                for (int ni = 0; ni < 4; ni++)
                    MMA16816(acc[mi][ni], ah[mi], bl[ni]);
        }
        __syncthreads();
    }

    #pragma unroll
    for (int mi = 0; mi < 4; mi++){
        long long r = row0 + wm*64 + mi*16 + g;
        #pragma unroll
        for (int ni = 0; ni < 4; ni++){
            long long cc = col0 + wn*32 + ni*8 + c2;
            float b0 = bias[cc], b1 = bias[cc + 1];
            float2 v0, v1;
            v0.x = acc[mi][ni][0] + b0; v0.y = acc[mi][ni][1] + b1;
            v1.x = acc[mi][ni][2] + b0; v1.y = acc[mi][ni][3] + b1;
            *(float2*)(C + r*V_ + cc)       = v0;
            *(float2*)(C + (r + 8)*V_ + cc) = v1;
        }
    }
}

// ---------------- launch -----------------------------------------------------
extern "C" void kernel_launch(void* const* d_in, const int* in_sizes, int n_in,
                              void* d_out, int out_size){
    const int*   y     = (const int*)  d_in[0];
    const float* h0    = (const float*)d_in[1];
    const float* c0    = (const float*)d_in[2];
    const float* enc   = (const float*)d_in[3];
    const float* emb   = (const float*)d_in[4];
    const float* Wx    = (const float*)d_in[5];
    const float* Wh    = (const float*)d_in[6];
    const float* bvec  = (const float*)d_in[7];
    const float* Wk    = (const float*)d_in[8];
    const float* Wq    = (const float*)d_in[9];
    const float* v_att = (const float*)d_in[10];
    const float* Wa    = (const float*)d_in[11];
    const float* Wout  = (const float*)d_in[12];
    const float* bout  = (const float*)d_in[13];
    float* out = (float*)d_out;

    void* p;
    cudaGetSymbolAddress(&p, g_keys); float* keys_p = (float*)p;
    __nv_bfloat16 *wxh, *wxl, *whh, *whl, *wqh, *wql, *wah, *wal, *bh, *bl;
    cudaGetSymbolAddress(&p, g_WxTh); wxh = (__nv_bfloat16*)p;
    cudaGetSymbolAddress(&p, g_WxTl); wxl = (__nv_bfloat16*)p;
    cudaGetSymbolAddress(&p, g_WhTh); whh = (__nv_bfloat16*)p;
    cudaGetSymbolAddress(&p, g_WhTl); whl = (__nv_bfloat16*)p;
    cudaGetSymbolAddress(&p, g_WqTh); wqh = (__nv_bfloat16*)p;
    cudaGetSymbolAddress(&p, g_WqTl); wql = (__nv_bfloat16*)p;
    cudaGetSymbolAddress(&p, g_WaTh); wah = (__nv_bfloat16*)p;
    cudaGetSymbolAddress(&p, g_WaTl); wal = (__nv_bfloat16*)p;
    cudaGetSymbolAddress(&p, g_Bh);   bh  = (__nv_bfloat16*)p;
    cudaGetSymbolAddress(&p, g_Bl);   bl  = (__nv_bfloat16*)p;

    cudaFuncSetAttribute(gemm_mma, cudaFuncAttributeMaxDynamicSharedMemorySize, GM_SMEM);
    cudaFuncSetAttribute(z_mma, cudaFuncAttributeMaxDynamicSharedMemorySize, Z_SMEM);
    cudaFuncSetAttribute(q_mma, cudaFuncAttributeMaxDynamicSharedMemorySize, Z_SMEM);
    cudaFuncSetAttribute(o_mma, cudaFuncAttributeMaxDynamicSharedMemorySize, Z_SMEM);

    init_hc<<<128, 256>>>(h0, c0);
    embed_gather<<<B_*T_, 128>>>(y, emb);

    // one-time weight splits (n-major bf16 hi/lo)
    split_wT<<<dim3(V_/32,  U_/32),    256>>>(Wout, bh,  bl,  U_,   V_);
    split_wT<<<dim3(4096/32, 1536/32), 256>>>(Wx,   wxh, wxl, 1536, 4096);
    split_wT<<<dim3(4096/32, 1024/32), 256>>>(Wh,   whh, whl, 1024, 4096);
    split_wT<<<dim3(1024/32, 1024/32), 256>>>(Wq,   wqh, wql, 1024, 1024);
    split_wT<<<dim3(1024/32, 2048/32), 256>>>(Wa,   wah, wal, 2048, 1024);

    // keys = enc @ Wk
    sgemm128<<<dim3((B_*S_)/128, U_/128), 256>>>(enc, Wk, nullptr, keys_p,
                                                 B_*S_, U_, U_);

    for (int t = 0; t < T_; t++){
        prep_step<<<32, 256>>>(t);
        z_mma<<<dim3(64, 5), 128, Z_SMEM>>>(t);
        lstm_pt<<<128, 256>>>(bvec);
        q_mma<<<dim3(16, 4), 128, Z_SMEM>>>();
        attn_step<<<32, 512>>>(enc, v_att);
        o_mma<<<dim3(16, 8), 128, Z_SMEM>>>();
    }
    prep_step<<<32, 256>>>(T_);   // emit Ah/Al for t = 63

    // tensor-core output GEMM
    gemm_mma<<<dim3((B_*T_)/128, V_/128), 256, GM_SMEM>>>(bout, out);
}